// round 13
// baseline (speedup 1.0000x reference)
#include <cuda_runtime.h>
#include <cuda_fp16.h>
#include <math.h>
#include <stdint.h>

#define N_NODES 16000
#define N_EDGES 256000
#define DIM 256
#define HEADS 8
#define HID 1024
#define LN_CNT (N_NODES * DIM)
#define LN_EPS 1e-5f
#define RSQRT_DH 0.17677669529663687f

// cat-weight table offsets (halves, per transformer block); all weights 2-cat
// except edge (1-cat)
#define OW_QKVS 0              // [1024, 512]
#define OW_E    524288         // [256, 256]
#define OW_1    589824         // [1024, 512]
#define OW_2    1114112        // [256, 2048]
#define WB      1638400

// ---------------- scratch -----------------------------------------------------
__device__ float    g_qkvs[(size_t)N_NODES * 1024];
__device__ __half   g_e_h3[3 * (size_t)N_EDGES * DIM];   // CSR-ordered
__device__ float    g_out[N_NODES * DIM];
__device__ float    g_y[N_NODES * DIM];
__device__ float    g_x[N_NODES * DIM];
__device__ double   g_red[12];
__device__ float    g_bqkvs[3 * 1024];
__device__ __half   g_xe_h[(size_t)N_EDGES * DIM];       // CSR-ordered gather
__device__ __half   g_x_cat[(size_t)N_NODES * 2 * DIM];
__device__ __half   g_y_cat[(size_t)N_NODES * 2 * DIM];
__device__ __half   g_h_cat[(size_t)N_NODES * 2 * HID];
__device__ __half   g_wt_cat[3 * WB];
// CSR
__device__ int      g_rowstart[N_NODES + 1];
__device__ int      g_cursor[N_NODES];
__device__ int      g_perm[N_EDGES];
__device__ int      g_src_s[N_EDGES];
__device__ float    g_invd_s[N_EDGES];

// ---------------- helpers -----------------------------------------------------
__device__ __forceinline__ uint32_t smem_u32(const void* p) {
    uint32_t a;
    asm("{ .reg .u64 t; cvta.to.shared.u64 t, %1; cvt.u32.u64 %0, t; }"
        : "=r"(a) : "l"(p));
    return a;
}
__device__ __forceinline__ uint32_t pack_h2(__half a, __half b) {
    __half2 h2 = __halves2half2(a, b);
    return *(uint32_t*)&h2;
}
__device__ __forceinline__ void cp16(uint32_t dst, const void* src) {
    asm volatile("cp.async.cg.shared.global [%0], [%1], 16;"
                 :: "r"(dst), "l"(src) : "memory");
}
__device__ __forceinline__ void ldsm_x4(uint32_t* r, uint32_t addr) {
    asm volatile("ldmatrix.sync.aligned.m8n8.x4.shared.b16 {%0,%1,%2,%3}, [%4];"
                 : "=r"(r[0]), "=r"(r[1]), "=r"(r[2]), "=r"(r[3]) : "r"(addr));
}
__device__ __forceinline__ void mma16816(float* c, const uint32_t* a, uint32_t b0, uint32_t b1) {
    asm volatile(
        "mma.sync.aligned.m16n8k16.row.col.f32.f16.f16.f32 "
        "{%0,%1,%2,%3}, {%4,%5,%6,%7}, {%8,%9}, {%0,%1,%2,%3};"
        : "+f"(c[0]), "+f"(c[1]), "+f"(c[2]), "+f"(c[3])
        : "r"(a[0]), "r"(a[1]), "r"(a[2]), "r"(a[3]), "r"(b0), "r"(b1));
}

// ================== node GEMM 128x128 (4 warps, 3-stage) ======================
#define NG_SMEM 98304

__device__ __forceinline__ void load_chunk_n(
    uint32_t st, const __half* __restrict__ A, const __half* __restrict__ B,
    size_t rowA0, size_t rowB0, int K3, int k0, int tid)
{
#pragma unroll
    for (int i = 0; i < 8; i++) {
        int u = tid + (i << 7);
        int row = u >> 3, kk = u & 7;
        uint32_t off = (uint32_t)(row * 128 + kk * 16);
        uint32_t sw = off ^ ((off >> 3) & 0x70);
        cp16(st + sw, A + (rowA0 + row) * (size_t)K3 + k0 + kk * 8);
        cp16(st + 16384 + sw, B + (rowB0 + row) * (size_t)K3 + k0 + kk * 8);
    }
}

__global__ __launch_bounds__(128) void gemm_mma(
    const __half* __restrict__ A, const __half* __restrict__ B,
    const float* __restrict__ bias,
    float* __restrict__ Cf, __half* __restrict__ Ccat,
    int M, int N, int K3, int relu)
{
    extern __shared__ __align__(128) char smem[];
    uint32_t sbase = smem_u32(smem);

    int tid = threadIdx.x, lane = tid & 31, wid = tid >> 5;
    int warpM = wid >> 1, warpN = wid & 1;
    int tN = blockIdx.x, tM = blockIdx.y;
    size_t rowA0 = (size_t)tM * 128;
    size_t rowB0 = (size_t)tN * 128;
    int nch = K3 >> 6;

    float acc[4][8][4];
#pragma unroll
    for (int i = 0; i < 4; i++)
#pragma unroll
        for (int j = 0; j < 8; j++)
#pragma unroll
            for (int t = 0; t < 4; t++) acc[i][j][t] = 0.f;

    load_chunk_n(sbase, A, B, rowA0, rowB0, K3, 0, tid);
    asm volatile("cp.async.commit_group;" ::: "memory");
    load_chunk_n(sbase + 32768, A, B, rowA0, rowB0, K3, 64, tid);
    asm volatile("cp.async.commit_group;" ::: "memory");

    for (int c = 0; c < nch; c++) {
        if (c + 2 < nch) {
            uint32_t sb = sbase + (uint32_t)((c + 2) % 3) * 32768u;
            load_chunk_n(sb, A, B, rowA0, rowB0, K3, (c + 2) << 6, tid);
            asm volatile("cp.async.commit_group;" ::: "memory");
            asm volatile("cp.async.wait_group 2;" ::: "memory");
        } else if (c + 1 < nch) {
            asm volatile("cp.async.wait_group 1;" ::: "memory");
        } else {
            asm volatile("cp.async.wait_group 0;" ::: "memory");
        }
        __syncthreads();

        uint32_t aB = sbase + (uint32_t)(c % 3) * 32768u;
        uint32_t bB = aB + 16384;
#pragma unroll
        for (int ks = 0; ks < 4; ks++) {
            uint32_t af[4][4], bf[4][4];
#pragma unroll
            for (int mf = 0; mf < 4; mf++) {
                int row = warpM * 64 + mf * 16 + (lane & 15);
                uint32_t off = (uint32_t)(row * 128 + ks * 32 + ((lane >> 4) << 4));
                off ^= (off >> 3) & 0x70;
                ldsm_x4(af[mf], aB + off);
            }
#pragma unroll
            for (int nf2 = 0; nf2 < 4; nf2++) {
                int row = warpN * 64 + nf2 * 16 + (lane & 15);
                uint32_t off = (uint32_t)(row * 128 + ks * 32 + ((lane >> 4) << 4));
                off ^= (off >> 3) & 0x70;
                ldsm_x4(bf[nf2], bB + off);
            }
#pragma unroll
            for (int mf = 0; mf < 4; mf++)
#pragma unroll
                for (int nf2 = 0; nf2 < 4; nf2++) {
                    mma16816(acc[mf][nf2 * 2],     af[mf], bf[nf2][0], bf[nf2][2]);
                    mma16816(acc[mf][nf2 * 2 + 1], af[mf], bf[nf2][1], bf[nf2][3]);
                }
        }
        __syncthreads();
    }

    int m0 = tM * 128 + warpM * 64;
    int n0 = tN * 128 + warpN * 64;
#pragma unroll
    for (int mf = 0; mf < 4; mf++) {
#pragma unroll
        for (int nf = 0; nf < 8; nf++) {
            int r = m0 + mf * 16 + (lane >> 2);
            int col = n0 + nf * 8 + ((lane & 3) << 1);
            float b0 = bias ? __ldg(bias + col) : 0.f;
            float b1 = bias ? __ldg(bias + col + 1) : 0.f;
            float v00 = acc[mf][nf][0] + b0, v01 = acc[mf][nf][1] + b1;
            float v10 = acc[mf][nf][2] + b0, v11 = acc[mf][nf][3] + b1;
            if (relu) {
                v00 = fmaxf(v00, 0.f); v01 = fmaxf(v01, 0.f);
                v10 = fmaxf(v10, 0.f); v11 = fmaxf(v11, 0.f);
            }
            if (Cf) {
                *(float2*)(Cf + (size_t)r * N + col) = make_float2(v00, v01);
                *(float2*)(Cf + (size_t)(r + 8) * N + col) = make_float2(v10, v11);
            }
            if (Ccat) {   // 2-cat [hi|lo]
                __half h00 = __float2half_rn(v00), h01 = __float2half_rn(v01);
                __half h10 = __float2half_rn(v10), h11 = __float2half_rn(v11);
                uint32_t uh0 = pack_h2(h00, h01), uh1 = pack_h2(h10, h11);
                uint32_t ul0 = pack_h2(__float2half_rn(v00 - __half2float(h00)),
                                       __float2half_rn(v01 - __half2float(h01)));
                uint32_t ul1 = pack_h2(__float2half_rn(v10 - __half2float(h10)),
                                       __float2half_rn(v11 - __half2float(h11)));
                size_t b0a = (size_t)r * 2 * N + col;
                size_t b1a = (size_t)(r + 8) * 2 * N + col;
                *(uint32_t*)(Ccat + b0a) = uh0;
                *(uint32_t*)(Ccat + b0a + N) = ul0;
                *(uint32_t*)(Ccat + b1a) = uh1;
                *(uint32_t*)(Ccat + b1a + N) = ul1;
            }
        }
    }
}

// ================== node GEMM 128x256 (8 warps, 2-stage) — FFN2 ===============
#define NG2_SMEM 98304

__device__ __forceinline__ void load_chunk_n2(
    uint32_t st, const __half* __restrict__ A, const __half* __restrict__ B,
    size_t rowA0, size_t rowB0, int K3, int k0, int tid)
{
#pragma unroll
    for (int i = 0; i < 4; i++) {
        int u = tid + (i << 8);
        int row = u >> 3, kk = u & 7;
        uint32_t off = (uint32_t)(row * 128 + kk * 16);
        uint32_t sw = off ^ ((off >> 3) & 0x70);
        cp16(st + sw, A + (rowA0 + row) * (size_t)K3 + k0 + kk * 8);
    }
#pragma unroll
    for (int i = 0; i < 8; i++) {
        int u = tid + (i << 8);
        int row = u >> 3, kk = u & 7;
        uint32_t off = (uint32_t)(row * 128 + kk * 16);
        uint32_t sw = off ^ ((off >> 3) & 0x70);
        cp16(st + 16384 + sw, B + (rowB0 + row) * (size_t)K3 + k0 + kk * 8);
    }
}

__global__ __launch_bounds__(256) void gemm_mma2(
    const __half* __restrict__ A, const __half* __restrict__ B,
    const float* __restrict__ bias, float* __restrict__ Cf,
    int M, int N, int K3)
{
    extern __shared__ __align__(128) char smem[];
    uint32_t sbase = smem_u32(smem);

    int tid = threadIdx.x, lane = tid & 31, wid = tid >> 5;
    int warpM = wid >> 2, warpN = wid & 3;
    int tN = blockIdx.x, tM = blockIdx.y;
    size_t rowA0 = (size_t)tM * 128;
    size_t rowB0 = (size_t)tN * 256;
    int nch = K3 >> 6;

    float acc[4][8][4];
#pragma unroll
    for (int i = 0; i < 4; i++)
#pragma unroll
        for (int j = 0; j < 8; j++)
#pragma unroll
            for (int t = 0; t < 4; t++) acc[i][j][t] = 0.f;

    load_chunk_n2(sbase, A, B, rowA0, rowB0, K3, 0, tid);
    asm volatile("cp.async.commit_group;" ::: "memory");

    for (int c = 0; c < nch; c++) {
        if (c + 1 < nch) {
            uint32_t sb = sbase + (uint32_t)((c + 1) & 1) * 49152u;
            load_chunk_n2(sb, A, B, rowA0, rowB0, K3, (c + 1) << 6, tid);
            asm volatile("cp.async.commit_group;" ::: "memory");
            asm volatile("cp.async.wait_group 1;" ::: "memory");
        } else {
            asm volatile("cp.async.wait_group 0;" ::: "memory");
        }
        __syncthreads();

        uint32_t aB = sbase + (uint32_t)(c & 1) * 49152u;
        uint32_t bB = aB + 16384;
#pragma unroll
        for (int ks = 0; ks < 4; ks++) {
            uint32_t af[4][4], bf[4][4];
#pragma unroll
            for (int mf = 0; mf < 4; mf++) {
                int row = warpM * 64 + mf * 16 + (lane & 15);
                uint32_t off = (uint32_t)(row * 128 + ks * 32 + ((lane >> 4) << 4));
                off ^= (off >> 3) & 0x70;
                ldsm_x4(af[mf], aB + off);
            }
#pragma unroll
            for (int nf2 = 0; nf2 < 4; nf2++) {
                int row = warpN * 64 + nf2 * 16 + (lane & 15);
                uint32_t off = (uint32_t)(row * 128 + ks * 32 + ((lane >> 4) << 4));
                off ^= (off >> 3) & 0x70;
                ldsm_x4(bf[nf2], bB + off);
            }
#pragma unroll
            for (int mf = 0; mf < 4; mf++)
#pragma unroll
                for (int nf2 = 0; nf2 < 4; nf2++) {
                    mma16816(acc[mf][nf2 * 2],     af[mf], bf[nf2][0], bf[nf2][2]);
                    mma16816(acc[mf][nf2 * 2 + 1], af[mf], bf[nf2][1], bf[nf2][3]);
                }
        }
        __syncthreads();
    }

    int m0 = tM * 128 + warpM * 64;
    int n0 = tN * 256 + warpN * 64;
#pragma unroll
    for (int mf = 0; mf < 4; mf++) {
#pragma unroll
        for (int nf = 0; nf < 8; nf++) {
            int r = m0 + mf * 16 + (lane >> 2);
            int col = n0 + nf * 8 + ((lane & 3) << 1);
            float b0 = bias ? __ldg(bias + col) : 0.f;
            float b1 = bias ? __ldg(bias + col + 1) : 0.f;
            *(float2*)(Cf + (size_t)r * N + col) =
                make_float2(acc[mf][nf][0] + b0, acc[mf][nf][1] + b1);
            *(float2*)(Cf + (size_t)(r + 8) * N + col) =
                make_float2(acc[mf][nf][2] + b0, acc[mf][nf][3] + b1);
        }
    }
}

// ================== edge GEMM: A-resident, all 3 blocks (1-cat) ===============
#define EG_SMEM 98304

__global__ __launch_bounds__(128) void gemm_edge(
    const __half* __restrict__ XE, const __half* __restrict__ WT,
    __half* __restrict__ EH)
{
    extern __shared__ __align__(128) char smem[];
    uint32_t sbase = smem_u32(smem);
    uint32_t bbase = sbase + 65536;

    int tid = threadIdx.x, lane = tid & 31, wid = tid >> 5;
    int warpM = wid >> 1, warpN = wid & 1;
    size_t rowA0 = (size_t)blockIdx.x * 128;

#pragma unroll
    for (int ch = 0; ch < 4; ch++) {
#pragma unroll
        for (int i = 0; i < 8; i++) {
            int u = tid + (i << 7);
            int row = u >> 3, kk = u & 7;
            uint32_t off = (uint32_t)(row * 128 + kk * 16);
            uint32_t sw = off ^ ((off >> 3) & 0x70);
            cp16(sbase + ch * 16384 + sw, XE + (rowA0 + row) * 256 + ch * 64 + kk * 8);
        }
    }
    {
#pragma unroll
        for (int i = 0; i < 8; i++) {
            int u = tid + (i << 7);
            int row = u >> 3, kk = u & 7;
            uint32_t off = (uint32_t)(row * 128 + kk * 16);
            uint32_t sw = off ^ ((off >> 3) & 0x70);
            cp16(bbase + sw, WT + OW_E + (size_t)row * 256 + kk * 8);
        }
    }
    asm volatile("cp.async.commit_group;" ::: "memory");

    float acc[4][8][4];
#pragma unroll
    for (int i = 0; i < 4; i++)
#pragma unroll
        for (int j = 0; j < 8; j++)
#pragma unroll
            for (int t = 0; t < 4; t++) acc[i][j][t] = 0.f;

    for (int it = 0; it < 24; it++) {
        if (it < 23) {
            int j = it + 1;
            int wt = j >> 2, ck = j & 3;
            int blkj = wt >> 1, nh = wt & 1;
            const __half* Bp = WT + (size_t)blkj * WB + OW_E;
            uint32_t bb = bbase + (uint32_t)(j & 1) * 16384u;
#pragma unroll
            for (int i = 0; i < 8; i++) {
                int u = tid + (i << 7);
                int row = u >> 3, kk = u & 7;
                uint32_t off = (uint32_t)(row * 128 + kk * 16);
                uint32_t sw = off ^ ((off >> 3) & 0x70);
                cp16(bb + sw, Bp + (size_t)(nh * 128 + row) * 256 + ck * 64 + kk * 8);
            }
            asm volatile("cp.async.commit_group;" ::: "memory");
            asm volatile("cp.async.wait_group 1;" ::: "memory");
        } else {
            asm volatile("cp.async.wait_group 0;" ::: "memory");
        }
        __syncthreads();

        int ck = it & 3;
        uint32_t aB = sbase + (uint32_t)ck * 16384u;
        uint32_t bB = bbase + (uint32_t)(it & 1) * 16384u;
#pragma unroll
        for (int ks = 0; ks < 4; ks++) {
            uint32_t af[4][4], bf[4][4];
#pragma unroll
            for (int mf = 0; mf < 4; mf++) {
                int row = warpM * 64 + mf * 16 + (lane & 15);
                uint32_t off = (uint32_t)(row * 128 + ks * 32 + ((lane >> 4) << 4));
                off ^= (off >> 3) & 0x70;
                ldsm_x4(af[mf], aB + off);
            }
#pragma unroll
            for (int nf2 = 0; nf2 < 4; nf2++) {
                int row = warpN * 64 + nf2 * 16 + (lane & 15);
                uint32_t off = (uint32_t)(row * 128 + ks * 32 + ((lane >> 4) << 4));
                off ^= (off >> 3) & 0x70;
                ldsm_x4(bf[nf2], bB + off);
            }
#pragma unroll
            for (int mf = 0; mf < 4; mf++)
#pragma unroll
                for (int nf2 = 0; nf2 < 4; nf2++) {
                    mma16816(acc[mf][nf2 * 2],     af[mf], bf[nf2][0], bf[nf2][2]);
                    mma16816(acc[mf][nf2 * 2 + 1], af[mf], bf[nf2][1], bf[nf2][3]);
                }
        }
        __syncthreads();

        if (ck == 3) {
            int wt = it >> 2;
            int blk = wt >> 1, nh = wt & 1;
            __half* out = EH + (size_t)blk * N_EDGES * DIM;
#pragma unroll
            for (int mf = 0; mf < 4; mf++) {
#pragma unroll
                for (int nf = 0; nf < 8; nf++) {
                    int r = (int)rowA0 + warpM * 64 + mf * 16 + (lane >> 2);
                    int col = nh * 128 + warpN * 64 + nf * 8 + ((lane & 3) << 1);
                    *(__half2*)(out + (size_t)r * DIM + col) =
                        __floats2half2_rn(acc[mf][nf][0], acc[mf][nf][1]);
                    *(__half2*)(out + (size_t)(r + 8) * DIM + col) =
                        __floats2half2_rn(acc[mf][nf][2], acc[mf][nf][3]);
#pragma unroll
                    for (int t = 0; t < 4; t++) acc[mf][nf][t] = 0.f;
                }
            }
        }
    }
}

// ---------------- CSR build ----------------------------------------------------
__global__ void zero_deg() {
    int i = blockIdx.x * blockDim.x + threadIdx.x;
    if (i < N_NODES) g_cursor[i] = 0;
    if (i < 12) g_red[i] = 0.0;
}
__global__ void hist_dst(const int* __restrict__ ei) {
    int i = blockIdx.x * blockDim.x + threadIdx.x;
    if (i < N_EDGES) atomicAdd(&g_cursor[ei[N_EDGES + i]], 1);
}
__global__ __launch_bounds__(1024) void scan16k() {
    __shared__ int warp_tot[32];
    int tid = threadIdx.x, lane = tid & 31, wid = tid >> 5;
    int base = tid * 16;
    int vals[16];
    int s = 0;
#pragma unroll
    for (int t = 0; t < 16; t++) {
        int idx = base + t;
        int v = (idx < N_NODES) ? g_cursor[idx] : 0;
        vals[t] = s;
        s += v;
    }
    int x = s;
#pragma unroll
    for (int o = 1; o < 32; o <<= 1) {
        int n = __shfl_up_sync(0xffffffffu, x, o);
        if (lane >= o) x += n;
    }
    if (lane == 31) warp_tot[wid] = x;
    __syncthreads();
    if (wid == 0) {
        int t = warp_tot[lane];
        int y = t;
#pragma unroll
        for (int o = 1; o < 32; o <<= 1) {
            int n = __shfl_up_sync(0xffffffffu, y, o);
            if (lane >= o) y += n;
        }
        warp_tot[lane] = y - t;
    }
    __syncthreads();
    int offset = warp_tot[wid] + (x - s);
#pragma unroll
    for (int t = 0; t < 16; t++) {
        int idx = base + t;
        if (idx < N_NODES) g_rowstart[idx] = offset + vals[t];
    }
    if (tid == 1023) g_rowstart[N_NODES] = offset + s;
    __syncthreads();
#pragma unroll
    for (int t = 0; t < 16; t++) {
        int idx = base + t;
        if (idx < N_NODES) g_cursor[idx] = g_rowstart[idx];
    }
}
__global__ void scatter_perm(const int* __restrict__ ei,
                             const float* __restrict__ xdist) {
    int i = blockIdx.x * blockDim.x + threadIdx.x;
    if (i < N_EDGES) {
        int d = ei[N_EDGES + i];
        int pos = atomicAdd(&g_cursor[d], 1);
        g_perm[pos] = i;
        g_src_s[pos] = ei[i];
        g_invd_s[pos] = 1.0f / xdist[i];
    }
}

// ---------------- converters / weight prep -------------------------------------
__global__ __launch_bounds__(256) void cvt_cat2(
    const float* __restrict__ s, __half* __restrict__ d, int K, int n4)
{
    int i = blockIdx.x * blockDim.x + threadIdx.x;
    if (i >= n4) return;
    int i4 = i * 4;
    int row = i4 / K, col = i4 % K;
    float4 v = ((const float4*)s)[i];
    float vv[4] = {v.x, v.y, v.z, v.w};
    __half h[4], l[4];
#pragma unroll
    for (int j = 0; j < 4; j++) {
        h[j] = __float2half_rn(vv[j]);
        l[j] = __float2half_rn(vv[j] - __half2float(h[j]));
    }
    size_t base = (size_t)row * 2 * K + col;
    *(uint2*)(d + base) = make_uint2(pack_h2(h[0], h[1]), pack_h2(h[2], h[3]));
    *(uint2*)(d + base + K) = make_uint2(pack_h2(l[0], l[1]), pack_h2(l[2], l[3]));
}

// gathered fp32->fp16: row i of dst = row perm[i] of src (256 cols)
__global__ __launch_bounds__(256) void cvt_h_gather(
    const float* __restrict__ s, __half* __restrict__ d)
{
    int tid = blockIdx.x * blockDim.x + threadIdx.x;
    int row = tid >> 6;
    int col = (tid & 63) * 4;
    if (row >= N_EDGES) return;
    int srow = g_perm[row];
    float4 v = *(const float4*)(s + (size_t)srow * DIM + col);
    *(uint2*)(d + (size_t)row * DIM + col) =
        make_uint2(pack_h2(__float2half_rn(v.x), __float2half_rn(v.y)),
                   pack_h2(__float2half_rn(v.z), __float2half_rn(v.w)));
}

// W [K,N] row-major -> out [N, cat*K]; cat=2: [Whi|Whi], cat=1: [Whi]
__global__ void tconv(const float* __restrict__ W, __half* __restrict__ out,
                      int K, int N, int cat)
{
    __shared__ float t[32][33];
    int tx = threadIdx.x, ty = threadIdx.y;
    int n0 = blockIdx.x * 32, k0 = blockIdx.y * 32;
#pragma unroll
    for (int r = 0; r < 4; r++)
        t[ty + 8 * r][tx] = W[(size_t)(k0 + ty + 8 * r) * N + n0 + tx];
    __syncthreads();
    int stride = cat * K;
#pragma unroll
    for (int r = 0; r < 4; r++) {
        int nl = ty + 8 * r;
        float v = t[tx][nl];
        size_t o = (size_t)(n0 + nl) * stride + k0 + tx;
        __half h = __float2half_rn(v);
        out[o] = h;
        if (cat == 2) out[o + K] = h;
    }
}

__global__ void pack_bias(const float* __restrict__ bq, const float* __restrict__ bk,
                          const float* __restrict__ bv, const float* __restrict__ bs)
{
    int b = blockIdx.x, t = threadIdx.x;
    float v = (t < 256) ? bq[b * 256 + t]
            : (t < 512) ? bk[b * 256 + t - 256]
            : (t < 768) ? bv[b * 256 + t - 512]
                        : bs[b * 256 + t - 768];
    g_bqkvs[b * 1024 + t] = v;
}

// ---------------- fused CSR attention + skip + residual + LN reduction ---------
__global__ __launch_bounds__(256) void attn_csr(
    const __half* __restrict__ eh, const float* __restrict__ x,
    float* __restrict__ y, double* __restrict__ red)
{
    int tid = threadIdx.x, lane = tid & 31, wid = tid >> 5;
    int node = blockIdx.x * 8 + wid;

    double ls = 0.0, lq = 0.0;
    if (node < N_NODES) {
        const float* qrow = g_qkvs + (size_t)node * 1024;
        float4 q0 = *(const float4*)(qrow + lane * 8);
        float4 q1 = *(const float4*)(qrow + lane * 8 + 4);

        int start = g_rowstart[node];
        int end   = g_rowstart[node + 1];

        float m0 = 0.f, m1 = 0.f, m2 = 0.f, m3 = 0.f;
        float m4 = 0.f, m5 = 0.f, m6 = 0.f, m7 = 0.f;
        float denom = 0.f;

        for (int j = start; j < end; j++) {
            int src = g_src_s[j];
            float invd = g_invd_s[j];

            const float* krow = g_qkvs + (size_t)src * 1024 + 256;
            const float* vrow = g_qkvs + (size_t)src * 1024 + 512;
            float4 k0 = *(const float4*)(krow + lane * 8);
            float4 k1 = *(const float4*)(krow + lane * 8 + 4);
            int4 evi = *(const int4*)(eh + (size_t)j * DIM + lane * 8);
            __half2* ehp = (__half2*)&evi;
            float2 e0 = __half22float2(ehp[0]), e1 = __half22float2(ehp[1]);
            float2 e2 = __half22float2(ehp[2]), e3 = __half22float2(ehp[3]);

            float p = 0.f;
            p = fmaf(q0.x, k0.x + e0.x, p);
            p = fmaf(q0.y, k0.y + e0.y, p);
            p = fmaf(q0.z, k0.z + e1.x, p);
            p = fmaf(q0.w, k0.w + e1.y, p);
            p = fmaf(q1.x, k1.x + e2.x, p);
            p = fmaf(q1.y, k1.y + e2.y, p);
            p = fmaf(q1.z, k1.z + e3.x, p);
            p = fmaf(q1.w, k1.w + e3.y, p);
            p += __shfl_xor_sync(0xffffffffu, p, 1);
            p += __shfl_xor_sync(0xffffffffu, p, 2);

            float ex = __expf(p * invd * RSQRT_DH);
            denom += ex;

            float4 v0 = *(const float4*)(vrow + lane * 8);
            float4 v1 = *(const float4*)(vrow + lane * 8 + 4);
            m0 = fmaf(v0.x + e0.x, ex, m0);
            m1 = fmaf(v0.y + e0.y, ex, m1);
            m2 = fmaf(v0.z + e1.x, ex, m2);
            m3 = fmaf(v0.w + e1.y, ex, m3);
            m4 = fmaf(v1.x + e2.x, ex, m4);
            m5 = fmaf(v1.y + e2.y, ex, m5);
            m6 = fmaf(v1.z + e3.x, ex, m6);
            m7 = fmaf(v1.w + e3.y, ex, m7);
        }

        float inv = 1.0f / (denom + 1e-16f);
        const float* xr = x + (size_t)node * 256 + lane * 8;
        const float* sk = g_qkvs + (size_t)node * 1024 + 768 + lane * 8;
        float4 xv0 = *(const float4*)(xr);
        float4 xv1 = *(const float4*)(xr + 4);
        float4 sk0 = *(const float4*)(sk);
        float4 sk1 = *(const float4*)(sk + 4);

        float r0 = xv0.x + sk0.x + m0 * inv;
        float r1 = xv0.y + sk0.y + m1 * inv;
        float r2 = xv0.z + sk0.z + m2 * inv;
        float r3 = xv0.w + sk0.w + m3 * inv;
        float r4 = xv1.x + sk1.x + m4 * inv;
        float r5 = xv1.y + sk1.y + m5 * inv;
        float r6 = xv1.z + sk1.z + m6 * inv;
        float r7 = xv1.w + sk1.w + m7 * inv;

        float* yp = y + (size_t)node * 256 + lane * 8;
        *(float4*)(yp)     = make_float4(r0, r1, r2, r3);
        *(float4*)(yp + 4) = make_float4(r4, r5, r6, r7);

        ls = (double)r0 + (double)r1 + (double)r2 + (double)r3 +
             (double)r4 + (double)r5 + (double)r6 + (double)r7;
        lq = (double)r0 * r0 + (double)r1 * r1 + (double)r2 * r2 + (double)r3 * r3 +
             (double)r4 * r4 + (double)r5 * r5 + (double)r6 * r6 + (double)r7 * r7;
    }

#pragma unroll
    for (int o = 16; o > 0; o >>= 1) {
        ls += __shfl_down_sync(0xffffffffu, ls, o);
        lq += __shfl_down_sync(0xffffffffu, lq, o);
    }
    __shared__ double shs[8], shq[8];
    if (lane == 0) { shs[wid] = ls; shq[wid] = lq; }
    __syncthreads();
    if (tid == 0) {
        double ts = 0, tq = 0;
#pragma unroll
        for (int k = 0; k < 8; k++) { ts += shs[k]; tq += shq[k]; }
        atomicAdd(&red[0], ts);
        atomicAdd(&red[1], tq);
    }
}

// ---------------- plain residual + DP reduction --------------------------------
__global__ __launch_bounds__(256) void resred(
    const float* __restrict__ a, const float* __restrict__ b,
    float* __restrict__ y, double* __restrict__ red)
{
    int i = blockIdx.x * blockDim.x + threadIdx.x;
    float4 av = ((const float4*)a)[i];
    float4 bv = ((const float4*)b)[i];
    float4 s = make_float4(av.x + bv.x, av.y + bv.y, av.z + bv.z, av.w + bv.w);
    ((float4*)y)[i] = s;

    double ls = (double)s.x + (double)s.y + (double)s.z + (double)s.w;
    double lq = (double)s.x * s.x + (double)s.y * s.y +
                (double)s.z * s.z + (double)s.w * s.w;
#pragma unroll
    for (int o = 16; o > 0; o >>= 1) {
        ls += __shfl_down_sync(0xffffffffu, ls, o);
        lq += __shfl_down_sync(0xffffffffu, lq, o);
    }
    __shared__ double shs[8], shq[8];
    int wid = threadIdx.x >> 5, lane = threadIdx.x & 31;
    if (lane == 0) { shs[wid] = ls; shq[wid] = lq; }
    __syncthreads();
    if (threadIdx.x == 0) {
        double ts = 0, tq = 0;
#pragma unroll
        for (int k = 0; k < 8; k++) { ts += shs[k]; tq += shq[k]; }
        atomicAdd(&red[0], ts);
        atomicAdd(&red[1], tq);
    }
}

// ---------------- graph layernorm apply + optional 2-cat fp16 emit -------------
__global__ __launch_bounds__(256) void lnapply(
    const float* __restrict__ y, const float* __restrict__ g,
    const float* __restrict__ b, float* __restrict__ o,
    __half* __restrict__ ocat, const double* __restrict__ red)
{
    int i = blockIdx.x * blockDim.x + threadIdx.x;
    double mean = red[0] / (double)LN_CNT;
    double var  = red[1] / (double)LN_CNT - mean * mean;
    if (var < 0) var = 0;
    float inv = 1.0f / ((float)sqrt(var) + LN_EPS);
    float mu = (float)mean;

    int i4 = i * 4;
    int c = i4 % DIM;
    int row = i4 / DIM;
    float4 yv = ((const float4*)y)[i];
    float4 gv = *(const float4*)(g + c);
    float4 bv = *(const float4*)(b + c);
    float4 r;
    r.x = (yv.x - mu) * inv * gv.x + bv.x;
    r.y = (yv.y - mu) * inv * gv.y + bv.y;
    r.z = (yv.z - mu) * inv * gv.z + bv.z;
    r.w = (yv.w - mu) * inv * gv.w + bv.w;
    ((float4*)o)[i] = r;

    if (ocat) {
        float vv[4] = {r.x, r.y, r.z, r.w};
        __half h[4], l[4];
#pragma unroll
        for (int j = 0; j < 4; j++) {
            h[j] = __float2half_rn(vv[j]);
            l[j] = __float2half_rn(vv[j] - __half2float(h[j]));
        }
        size_t base = (size_t)row * 2 * DIM + c;
        *(uint2*)(ocat + base) = make_uint2(pack_h2(h[0], h[1]), pack_h2(h[2], h[3]));
        *(uint2*)(ocat + base + DIM) = make_uint2(pack_h2(l[0], l[1]), pack_h2(l[2], l[3]));
    }
}

// ---------------- host orchestration -------------------------------------------
extern "C" void kernel_launch(void* const* d_in, const int* in_sizes, int n_in,
                              void* d_out, int out_size)
{
    const float* x_in   = (const float*)d_in[0];
    const int*   ei     = (const int*)d_in[1];
    const float* x_edge = (const float*)d_in[2];
    const float* x_dist = (const float*)d_in[3];
    const float* Wq_a   = (const float*)d_in[4];
    const float* bq_a   = (const float*)d_in[5];
    const float* Wk_a   = (const float*)d_in[6];
    const float* bk_a   = (const float*)d_in[7];
    const float* Wv_a   = (const float*)d_in[8];
    const float* bv_a   = (const float*)d_in[9];
    const float* We_a   = (const float*)d_in[10];
    const float* Ws_a   = (const float*)d_in[11];
    const float* bs_a   = (const float*)d_in[12];
    const float* g1_a   = (const float*)d_in[13];
    const float* b1_a   = (const float*)d_in[14];
    const float* W1_a   = (const float*)d_in[15];
    const float* c1_a   = (const float*)d_in[16];
    const float* W2_a   = (const float*)d_in[17];
    const float* c2_a   = (const float*)d_in[18];
    const float* g2_a   = (const float*)d_in[19];
    const float* b2_a   = (const float*)d_in[20];

    static int smem_set = 0;
    if (!smem_set) {
        cudaFuncSetAttribute(gemm_mma, cudaFuncAttributeMaxDynamicSharedMemorySize, NG_SMEM);
        cudaFuncSetAttribute(gemm_mma2, cudaFuncAttributeMaxDynamicSharedMemorySize, NG2_SMEM);
        cudaFuncSetAttribute(gemm_edge, cudaFuncAttributeMaxDynamicSharedMemorySize, EG_SMEM);
        smem_set = 1;
    }

    float *qkvs_, *out_, *y_, *x_, *bqkvs_;
    double* red_;
    __half *eh3_, *xeh_, *xc_, *yc_, *hc_, *wt_;
    cudaGetSymbolAddress((void**)&qkvs_, g_qkvs);
    cudaGetSymbolAddress((void**)&eh3_,  g_e_h3);
    cudaGetSymbolAddress((void**)&out_,  g_out);
    cudaGetSymbolAddress((void**)&y_,    g_y);
    cudaGetSymbolAddress((void**)&x_,    g_x);
    cudaGetSymbolAddress((void**)&red_,  g_red);
    cudaGetSymbolAddress((void**)&bqkvs_, g_bqkvs);
    cudaGetSymbolAddress((void**)&xeh_,  g_xe_h);
    cudaGetSymbolAddress((void**)&xc_,   g_x_cat);
    cudaGetSymbolAddress((void**)&yc_,   g_y_cat);
    cudaGetSymbolAddress((void**)&hc_,   g_h_cat);
    cudaGetSymbolAddress((void**)&wt_,   g_wt_cat);

    const int elem4 = LN_CNT / 4;

    // CSR build (also zeroes the 12 LN accumulators)
    zero_deg<<<(N_NODES + 255) / 256, 256>>>();
    hist_dst<<<(N_EDGES + 255) / 256, 256>>>(ei);
    scan16k<<<1, 1024>>>();
    scatter_perm<<<(N_EDGES + 255) / 256, 256>>>(ei, x_dist);

    // conversions + weight prep
    cvt_cat2<<<(elem4 + 255) / 256, 256>>>(x_in, xc_, DIM, elem4);
    cvt_h_gather<<<(N_EDGES * 64) / 256, 256>>>(x_edge, xeh_);
    pack_bias<<<3, 1024>>>(bq_a, bk_a, bv_a, bs_a);
    dim3 tb(32, 8);
    for (int b = 0; b < 3; b++) {
        size_t wb = (size_t)b * WB;
        __half* wq = wt_ + wb + OW_QKVS;
        tconv<<<dim3(8, 8),  tb>>>(Wq_a + (size_t)b * DIM * DIM, wq,             DIM, DIM, 2);
        tconv<<<dim3(8, 8),  tb>>>(Wk_a + (size_t)b * DIM * DIM, wq + 256 * 512, DIM, DIM, 2);
        tconv<<<dim3(8, 8),  tb>>>(Wv_a + (size_t)b * DIM * DIM, wq + 512 * 512, DIM, DIM, 2);
        tconv<<<dim3(8, 8),  tb>>>(Ws_a + (size_t)b * DIM * DIM, wq + 768 * 512, DIM, DIM, 2);
        tconv<<<dim3(8, 8),  tb>>>(We_a + (size_t)b * DIM * DIM, wt_ + wb + OW_E, DIM, DIM, 1);
        tconv<<<dim3(32, 8), tb>>>(W1_a + (size_t)b * DIM * HID, wt_ + wb + OW_1, DIM, HID, 2);
        tconv<<<dim3(8, 32), tb>>>(W2_a + (size_t)b * HID * DIM, wt_ + wb + OW_2, HID, DIM, 2);
    }

    // edge projections for all blocks, output already CSR-ordered
    gemm_edge<<<N_EDGES / 128, 128, EG_SMEM>>>(xeh_, wt_, eh3_);

    const float* xcur = x_in;
    for (int blk = 0; blk < 3; blk++) {
        size_t wb = (size_t)blk * WB;
        const float* g1 = g1_a + blk * DIM;
        const float* b1 = b1_a + blk * DIM;
        const float* c1 = c1_a + blk * HID;
        const float* c2 = c2_a + blk * DIM;
        const float* g2 = g2_a + blk * DIM;
        const float* b2 = b2_a + blk * DIM;
        double* redb = red_ + blk * 4;

        gemm_mma<<<dim3(8, 125), 128, NG_SMEM>>>(
            xc_, wt_ + wb + OW_QKVS, bqkvs_ + blk * 1024,
            qkvs_, nullptr, N_NODES, 1024, 512, 0);

        attn_csr<<<N_NODES / 8, 256>>>(eh3_ + (size_t)blk * N_EDGES * DIM,
                                       xcur, y_, redb + 0);
        lnapply<<<elem4 / 256, 256>>>(y_, g1, b1, y_, yc_, redb + 0);

        gemm_mma<<<dim3(8, 125), 128, NG_SMEM>>>(
            yc_, wt_ + wb + OW_1, c1, nullptr, hc_, N_NODES, HID, 512, 1);
        gemm_mma2<<<dim3(1, 125), 256, NG2_SMEM>>>(
            hc_, wt_ + wb + OW_2, c2, out_, N_NODES, DIM, 2048);

        resred<<<elem4 / 256, 256>>>(y_, out_, out_, redb + 2);
        float* xdst = (blk == 2) ? (float*)d_out : x_;
        __half* xcat = (blk == 2) ? nullptr : xc_;
        lnapply<<<elem4 / 256, 256>>>(out_, g2, b2, xdst, xcat, redb + 2);

        xcur = x_;
    }
}

// round 14
// speedup vs baseline: 1.5198x; 1.5198x over previous
#include <cuda_runtime.h>
#include <cuda_fp16.h>
#include <math.h>
#include <stdint.h>

#define N_NODES 16000
#define N_EDGES 256000
#define DIM 256
#define HEADS 8
#define HID 1024
#define LN_CNT (N_NODES * DIM)
#define LN_EPS 1e-5f
#define RSQRT_DH 0.17677669529663687f

// cat-weight table offsets (halves, per transformer block); all weights 2-cat
// except edge (1-cat)
#define OW_QKVS 0              // [1024, 512]
#define OW_E    524288         // [256, 256]
#define OW_1    589824         // [1024, 512]
#define OW_2    1114112        // [256, 2048]
#define WB      1638400

// ---------------- scratch -----------------------------------------------------
__device__ float    g_qkvs[(size_t)N_NODES * 1024];
__device__ __half   g_e_h3[3 * (size_t)N_EDGES * DIM];   // CSR-ordered
__device__ float    g_out[N_NODES * DIM];
__device__ float    g_y[N_NODES * DIM];
__device__ float    g_x[N_NODES * DIM];
__device__ double   g_red[12];
__device__ float    g_bqkvs[3 * 1024];
__device__ __half   g_xe_h[(size_t)N_EDGES * DIM];       // CSR-ordered gather
__device__ __half   g_x_cat[(size_t)N_NODES * 2 * DIM];
__device__ __half   g_y_cat[(size_t)N_NODES * 2 * DIM];
__device__ __half   g_h_cat[(size_t)N_NODES * 2 * HID];
__device__ __half   g_wt_cat[3 * WB];
// CSR
__device__ int      g_rowstart[N_NODES + 1];
__device__ int      g_cursor[N_NODES];
__device__ int      g_perm[N_EDGES];
__device__ int      g_src_s[N_EDGES];
__device__ float    g_invd_s[N_EDGES];

// ---------------- helpers -----------------------------------------------------
__device__ __forceinline__ uint32_t smem_u32(const void* p) {
    uint32_t a;
    asm("{ .reg .u64 t; cvta.to.shared.u64 t, %1; cvt.u32.u64 %0, t; }"
        : "=r"(a) : "l"(p));
    return a;
}
__device__ __forceinline__ uint32_t pack_h2(__half a, __half b) {
    __half2 h2 = __halves2half2(a, b);
    return *(uint32_t*)&h2;
}
__device__ __forceinline__ void cp16(uint32_t dst, const void* src) {
    asm volatile("cp.async.cg.shared.global [%0], [%1], 16;"
                 :: "r"(dst), "l"(src) : "memory");
}
__device__ __forceinline__ void ldsm_x4(uint32_t* r, uint32_t addr) {
    asm volatile("ldmatrix.sync.aligned.m8n8.x4.shared.b16 {%0,%1,%2,%3}, [%4];"
                 : "=r"(r[0]), "=r"(r[1]), "=r"(r[2]), "=r"(r[3]) : "r"(addr));
}
__device__ __forceinline__ void mma16816(float* c, const uint32_t* a, uint32_t b0, uint32_t b1) {
    asm volatile(
        "mma.sync.aligned.m16n8k16.row.col.f32.f16.f16.f32 "
        "{%0,%1,%2,%3}, {%4,%5,%6,%7}, {%8,%9}, {%0,%1,%2,%3};"
        : "+f"(c[0]), "+f"(c[1]), "+f"(c[2]), "+f"(c[3])
        : "r"(a[0]), "r"(a[1]), "r"(a[2]), "r"(a[3]), "r"(b0), "r"(b1));
}

// ================== node GEMM 128x128 (4 warps, 3-stage) ======================
#define NG_SMEM 98304

__device__ __forceinline__ void load_chunk_n(
    uint32_t st, const __half* __restrict__ A, const __half* __restrict__ B,
    size_t rowA0, size_t rowB0, int K3, int k0, int tid)
{
#pragma unroll
    for (int i = 0; i < 8; i++) {
        int u = tid + (i << 7);
        int row = u >> 3, kk = u & 7;
        uint32_t off = (uint32_t)(row * 128 + kk * 16);
        uint32_t sw = off ^ ((off >> 3) & 0x70);
        cp16(st + sw, A + (rowA0 + row) * (size_t)K3 + k0 + kk * 8);
        cp16(st + 16384 + sw, B + (rowB0 + row) * (size_t)K3 + k0 + kk * 8);
    }
}

__global__ __launch_bounds__(128) void gemm_mma(
    const __half* __restrict__ A, const __half* __restrict__ B,
    const float* __restrict__ bias,
    float* __restrict__ Cf, __half* __restrict__ Ccat,
    int M, int N, int K3, int relu)
{
    extern __shared__ __align__(128) char smem[];
    uint32_t sbase = smem_u32(smem);

    int tid = threadIdx.x, lane = tid & 31, wid = tid >> 5;
    int warpM = wid >> 1, warpN = wid & 1;
    int tN = blockIdx.x, tM = blockIdx.y;
    size_t rowA0 = (size_t)tM * 128;
    size_t rowB0 = (size_t)tN * 128;
    int nch = K3 >> 6;

    float acc[4][8][4];
#pragma unroll
    for (int i = 0; i < 4; i++)
#pragma unroll
        for (int j = 0; j < 8; j++)
#pragma unroll
            for (int t = 0; t < 4; t++) acc[i][j][t] = 0.f;

    load_chunk_n(sbase, A, B, rowA0, rowB0, K3, 0, tid);
    asm volatile("cp.async.commit_group;" ::: "memory");
    load_chunk_n(sbase + 32768, A, B, rowA0, rowB0, K3, 64, tid);
    asm volatile("cp.async.commit_group;" ::: "memory");

    for (int c = 0; c < nch; c++) {
        if (c + 2 < nch) {
            uint32_t sb = sbase + (uint32_t)((c + 2) % 3) * 32768u;
            load_chunk_n(sb, A, B, rowA0, rowB0, K3, (c + 2) << 6, tid);
            asm volatile("cp.async.commit_group;" ::: "memory");
            asm volatile("cp.async.wait_group 2;" ::: "memory");
        } else if (c + 1 < nch) {
            asm volatile("cp.async.wait_group 1;" ::: "memory");
        } else {
            asm volatile("cp.async.wait_group 0;" ::: "memory");
        }
        __syncthreads();

        uint32_t aB = sbase + (uint32_t)(c % 3) * 32768u;
        uint32_t bB = aB + 16384;
#pragma unroll
        for (int ks = 0; ks < 4; ks++) {
            uint32_t af[4][4], bf[4][4];
#pragma unroll
            for (int mf = 0; mf < 4; mf++) {
                int row = warpM * 64 + mf * 16 + (lane & 15);
                uint32_t off = (uint32_t)(row * 128 + ks * 32 + ((lane >> 4) << 4));
                off ^= (off >> 3) & 0x70;
                ldsm_x4(af[mf], aB + off);
            }
#pragma unroll
            for (int nf2 = 0; nf2 < 4; nf2++) {
                int row = warpN * 64 + nf2 * 16 + (lane & 15);
                uint32_t off = (uint32_t)(row * 128 + ks * 32 + ((lane >> 4) << 4));
                off ^= (off >> 3) & 0x70;
                ldsm_x4(bf[nf2], bB + off);
            }
#pragma unroll
            for (int mf = 0; mf < 4; mf++)
#pragma unroll
                for (int nf2 = 0; nf2 < 4; nf2++) {
                    mma16816(acc[mf][nf2 * 2],     af[mf], bf[nf2][0], bf[nf2][2]);
                    mma16816(acc[mf][nf2 * 2 + 1], af[mf], bf[nf2][1], bf[nf2][3]);
                }
        }
        __syncthreads();
    }

    int m0 = tM * 128 + warpM * 64;
    int n0 = tN * 128 + warpN * 64;
#pragma unroll
    for (int mf = 0; mf < 4; mf++) {
#pragma unroll
        for (int nf = 0; nf < 8; nf++) {
            int r = m0 + mf * 16 + (lane >> 2);
            int col = n0 + nf * 8 + ((lane & 3) << 1);
            float b0 = bias ? __ldg(bias + col) : 0.f;
            float b1 = bias ? __ldg(bias + col + 1) : 0.f;
            float v00 = acc[mf][nf][0] + b0, v01 = acc[mf][nf][1] + b1;
            float v10 = acc[mf][nf][2] + b0, v11 = acc[mf][nf][3] + b1;
            if (relu) {
                v00 = fmaxf(v00, 0.f); v01 = fmaxf(v01, 0.f);
                v10 = fmaxf(v10, 0.f); v11 = fmaxf(v11, 0.f);
            }
            if (Cf) {
                *(float2*)(Cf + (size_t)r * N + col) = make_float2(v00, v01);
                *(float2*)(Cf + (size_t)(r + 8) * N + col) = make_float2(v10, v11);
            }
            if (Ccat) {   // 2-cat [hi|lo]
                __half h00 = __float2half_rn(v00), h01 = __float2half_rn(v01);
                __half h10 = __float2half_rn(v10), h11 = __float2half_rn(v11);
                uint32_t uh0 = pack_h2(h00, h01), uh1 = pack_h2(h10, h11);
                uint32_t ul0 = pack_h2(__float2half_rn(v00 - __half2float(h00)),
                                       __float2half_rn(v01 - __half2float(h01)));
                uint32_t ul1 = pack_h2(__float2half_rn(v10 - __half2float(h10)),
                                       __float2half_rn(v11 - __half2float(h11)));
                size_t b0a = (size_t)r * 2 * N + col;
                size_t b1a = (size_t)(r + 8) * 2 * N + col;
                *(uint32_t*)(Ccat + b0a) = uh0;
                *(uint32_t*)(Ccat + b0a + N) = ul0;
                *(uint32_t*)(Ccat + b1a) = uh1;
                *(uint32_t*)(Ccat + b1a + N) = ul1;
            }
        }
    }
}

// ================== node GEMM 128x256 (8 warps, 2-stage) — FFN2 ===============
#define NG2_SMEM 98304

__device__ __forceinline__ void load_chunk_n2(
    uint32_t st, const __half* __restrict__ A, const __half* __restrict__ B,
    size_t rowA0, size_t rowB0, int K3, int k0, int tid)
{
#pragma unroll
    for (int i = 0; i < 4; i++) {
        int u = tid + (i << 8);
        int row = u >> 3, kk = u & 7;
        uint32_t off = (uint32_t)(row * 128 + kk * 16);
        uint32_t sw = off ^ ((off >> 3) & 0x70);
        cp16(st + sw, A + (rowA0 + row) * (size_t)K3 + k0 + kk * 8);
    }
#pragma unroll
    for (int i = 0; i < 8; i++) {
        int u = tid + (i << 8);
        int row = u >> 3, kk = u & 7;
        uint32_t off = (uint32_t)(row * 128 + kk * 16);
        uint32_t sw = off ^ ((off >> 3) & 0x70);
        cp16(st + 16384 + sw, B + (rowB0 + row) * (size_t)K3 + k0 + kk * 8);
    }
}

__global__ __launch_bounds__(256) void gemm_mma2(
    const __half* __restrict__ A, const __half* __restrict__ B,
    const float* __restrict__ bias, float* __restrict__ Cf,
    int M, int N, int K3)
{
    extern __shared__ __align__(128) char smem[];
    uint32_t sbase = smem_u32(smem);

    int tid = threadIdx.x, lane = tid & 31, wid = tid >> 5;
    int warpM = wid >> 2, warpN = wid & 3;
    int tN = blockIdx.x, tM = blockIdx.y;
    size_t rowA0 = (size_t)tM * 128;
    size_t rowB0 = (size_t)tN * 256;
    int nch = K3 >> 6;

    float acc[4][8][4];
#pragma unroll
    for (int i = 0; i < 4; i++)
#pragma unroll
        for (int j = 0; j < 8; j++)
#pragma unroll
            for (int t = 0; t < 4; t++) acc[i][j][t] = 0.f;

    load_chunk_n2(sbase, A, B, rowA0, rowB0, K3, 0, tid);
    asm volatile("cp.async.commit_group;" ::: "memory");

    for (int c = 0; c < nch; c++) {
        if (c + 1 < nch) {
            uint32_t sb = sbase + (uint32_t)((c + 1) & 1) * 49152u;
            load_chunk_n2(sb, A, B, rowA0, rowB0, K3, (c + 1) << 6, tid);
            asm volatile("cp.async.commit_group;" ::: "memory");
            asm volatile("cp.async.wait_group 1;" ::: "memory");
        } else {
            asm volatile("cp.async.wait_group 0;" ::: "memory");
        }
        __syncthreads();

        uint32_t aB = sbase + (uint32_t)(c & 1) * 49152u;
        uint32_t bB = aB + 16384;
#pragma unroll
        for (int ks = 0; ks < 4; ks++) {
            uint32_t af[4][4], bf[4][4];
#pragma unroll
            for (int mf = 0; mf < 4; mf++) {
                int row = warpM * 64 + mf * 16 + (lane & 15);
                uint32_t off = (uint32_t)(row * 128 + ks * 32 + ((lane >> 4) << 4));
                off ^= (off >> 3) & 0x70;
                ldsm_x4(af[mf], aB + off);
            }
#pragma unroll
            for (int nf2 = 0; nf2 < 4; nf2++) {
                int row = warpN * 64 + nf2 * 16 + (lane & 15);
                uint32_t off = (uint32_t)(row * 128 + ks * 32 + ((lane >> 4) << 4));
                off ^= (off >> 3) & 0x70;
                ldsm_x4(bf[nf2], bB + off);
            }
#pragma unroll
            for (int mf = 0; mf < 4; mf++)
#pragma unroll
                for (int nf2 = 0; nf2 < 4; nf2++) {
                    mma16816(acc[mf][nf2 * 2],     af[mf], bf[nf2][0], bf[nf2][2]);
                    mma16816(acc[mf][nf2 * 2 + 1], af[mf], bf[nf2][1], bf[nf2][3]);
                }
        }
        __syncthreads();
    }

    int m0 = tM * 128 + warpM * 64;
    int n0 = tN * 256 + warpN * 64;
#pragma unroll
    for (int mf = 0; mf < 4; mf++) {
#pragma unroll
        for (int nf = 0; nf < 8; nf++) {
            int r = m0 + mf * 16 + (lane >> 2);
            int col = n0 + nf * 8 + ((lane & 3) << 1);
            float b0 = bias ? __ldg(bias + col) : 0.f;
            float b1 = bias ? __ldg(bias + col + 1) : 0.f;
            *(float2*)(Cf + (size_t)r * N + col) =
                make_float2(acc[mf][nf][0] + b0, acc[mf][nf][1] + b1);
            *(float2*)(Cf + (size_t)(r + 8) * N + col) =
                make_float2(acc[mf][nf][2] + b0, acc[mf][nf][3] + b1);
        }
    }
}

// ================== edge GEMM: A-resident, all 3 blocks (1-cat) ===============
#define EG_SMEM 98304

__global__ __launch_bounds__(128) void gemm_edge(
    const __half* __restrict__ XE, const __half* __restrict__ WT,
    __half* __restrict__ EH)
{
    extern __shared__ __align__(128) char smem[];
    uint32_t sbase = smem_u32(smem);
    uint32_t bbase = sbase + 65536;

    int tid = threadIdx.x, lane = tid & 31, wid = tid >> 5;
    int warpM = wid >> 1, warpN = wid & 1;
    size_t rowA0 = (size_t)blockIdx.x * 128;

#pragma unroll
    for (int ch = 0; ch < 4; ch++) {
#pragma unroll
        for (int i = 0; i < 8; i++) {
            int u = tid + (i << 7);
            int row = u >> 3, kk = u & 7;
            uint32_t off = (uint32_t)(row * 128 + kk * 16);
            uint32_t sw = off ^ ((off >> 3) & 0x70);
            cp16(sbase + ch * 16384 + sw, XE + (rowA0 + row) * 256 + ch * 64 + kk * 8);
        }
    }
    {
#pragma unroll
        for (int i = 0; i < 8; i++) {
            int u = tid + (i << 7);
            int row = u >> 3, kk = u & 7;
            uint32_t off = (uint32_t)(row * 128 + kk * 16);
            uint32_t sw = off ^ ((off >> 3) & 0x70);
            cp16(bbase + sw, WT + OW_E + (size_t)row * 256 + kk * 8);
        }
    }
    asm volatile("cp.async.commit_group;" ::: "memory");

    float acc[4][8][4];
#pragma unroll
    for (int i = 0; i < 4; i++)
#pragma unroll
        for (int j = 0; j < 8; j++)
#pragma unroll
            for (int t = 0; t < 4; t++) acc[i][j][t] = 0.f;

    for (int it = 0; it < 24; it++) {
        if (it < 23) {
            int j = it + 1;
            int wt = j >> 2, ck = j & 3;
            int blkj = wt >> 1, nh = wt & 1;
            const __half* Bp = WT + (size_t)blkj * WB + OW_E;
            uint32_t bb = bbase + (uint32_t)(j & 1) * 16384u;
#pragma unroll
            for (int i = 0; i < 8; i++) {
                int u = tid + (i << 7);
                int row = u >> 3, kk = u & 7;
                uint32_t off = (uint32_t)(row * 128 + kk * 16);
                uint32_t sw = off ^ ((off >> 3) & 0x70);
                cp16(bb + sw, Bp + (size_t)(nh * 128 + row) * 256 + ck * 64 + kk * 8);
            }
            asm volatile("cp.async.commit_group;" ::: "memory");
            asm volatile("cp.async.wait_group 1;" ::: "memory");
        } else {
            asm volatile("cp.async.wait_group 0;" ::: "memory");
        }
        __syncthreads();

        int ck = it & 3;
        uint32_t aB = sbase + (uint32_t)ck * 16384u;
        uint32_t bB = bbase + (uint32_t)(it & 1) * 16384u;
#pragma unroll
        for (int ks = 0; ks < 4; ks++) {
            uint32_t af[4][4], bf[4][4];
#pragma unroll
            for (int mf = 0; mf < 4; mf++) {
                int row = warpM * 64 + mf * 16 + (lane & 15);
                uint32_t off = (uint32_t)(row * 128 + ks * 32 + ((lane >> 4) << 4));
                off ^= (off >> 3) & 0x70;
                ldsm_x4(af[mf], aB + off);
            }
#pragma unroll
            for (int nf2 = 0; nf2 < 4; nf2++) {
                int row = warpN * 64 + nf2 * 16 + (lane & 15);
                uint32_t off = (uint32_t)(row * 128 + ks * 32 + ((lane >> 4) << 4));
                off ^= (off >> 3) & 0x70;
                ldsm_x4(bf[nf2], bB + off);
            }
#pragma unroll
            for (int mf = 0; mf < 4; mf++)
#pragma unroll
                for (int nf2 = 0; nf2 < 4; nf2++) {
                    mma16816(acc[mf][nf2 * 2],     af[mf], bf[nf2][0], bf[nf2][2]);
                    mma16816(acc[mf][nf2 * 2 + 1], af[mf], bf[nf2][1], bf[nf2][3]);
                }
        }
        __syncthreads();

        if (ck == 3) {
            int wt = it >> 2;
            int blk = wt >> 1, nh = wt & 1;
            __half* out = EH + (size_t)blk * N_EDGES * DIM;
#pragma unroll
            for (int mf = 0; mf < 4; mf++) {
#pragma unroll
                for (int nf = 0; nf < 8; nf++) {
                    int r = (int)rowA0 + warpM * 64 + mf * 16 + (lane >> 2);
                    int col = nh * 128 + warpN * 64 + nf * 8 + ((lane & 3) << 1);
                    *(__half2*)(out + (size_t)r * DIM + col) =
                        __floats2half2_rn(acc[mf][nf][0], acc[mf][nf][1]);
                    *(__half2*)(out + (size_t)(r + 8) * DIM + col) =
                        __floats2half2_rn(acc[mf][nf][2], acc[mf][nf][3]);
#pragma unroll
                    for (int t = 0; t < 4; t++) acc[mf][nf][t] = 0.f;
                }
            }
        }
    }
}

// ---------------- CSR build ----------------------------------------------------
__global__ void zero_deg() {
    int i = blockIdx.x * blockDim.x + threadIdx.x;
    if (i < N_NODES) g_cursor[i] = 0;
    if (i < 12) g_red[i] = 0.0;
}
__global__ void hist_dst(const int* __restrict__ ei) {
    int i = blockIdx.x * blockDim.x + threadIdx.x;
    if (i < N_EDGES) atomicAdd(&g_cursor[ei[N_EDGES + i]], 1);
}
__global__ __launch_bounds__(1024) void scan16k() {
    __shared__ int warp_tot[32];
    int tid = threadIdx.x, lane = tid & 31, wid = tid >> 5;
    int base = tid * 16;
    int vals[16];
    int s = 0;
#pragma unroll
    for (int t = 0; t < 16; t++) {
        int idx = base + t;
        int v = (idx < N_NODES) ? g_cursor[idx] : 0;
        vals[t] = s;
        s += v;
    }
    int x = s;
#pragma unroll
    for (int o = 1; o < 32; o <<= 1) {
        int n = __shfl_up_sync(0xffffffffu, x, o);
        if (lane >= o) x += n;
    }
    if (lane == 31) warp_tot[wid] = x;
    __syncthreads();
    if (wid == 0) {
        int t = warp_tot[lane];
        int y = t;
#pragma unroll
        for (int o = 1; o < 32; o <<= 1) {
            int n = __shfl_up_sync(0xffffffffu, y, o);
            if (lane >= o) y += n;
        }
        warp_tot[lane] = y - t;
    }
    __syncthreads();
    int offset = warp_tot[wid] + (x - s);
#pragma unroll
    for (int t = 0; t < 16; t++) {
        int idx = base + t;
        if (idx < N_NODES) g_rowstart[idx] = offset + vals[t];
    }
    if (tid == 1023) g_rowstart[N_NODES] = offset + s;
    __syncthreads();
#pragma unroll
    for (int t = 0; t < 16; t++) {
        int idx = base + t;
        if (idx < N_NODES) g_cursor[idx] = g_rowstart[idx];
    }
}
__global__ void scatter_perm(const int* __restrict__ ei,
                             const float* __restrict__ xdist) {
    int i = blockIdx.x * blockDim.x + threadIdx.x;
    if (i < N_EDGES) {
        int d = ei[N_EDGES + i];
        int pos = atomicAdd(&g_cursor[d], 1);
        g_perm[pos] = i;
        g_src_s[pos] = ei[i];
        g_invd_s[pos] = 1.0f / xdist[i];
    }
}

// ---------------- converters / weight prep -------------------------------------
__global__ __launch_bounds__(256) void cvt_cat2(
    const float* __restrict__ s, __half* __restrict__ d, int K, int n4)
{
    int i = blockIdx.x * blockDim.x + threadIdx.x;
    if (i >= n4) return;
    int i4 = i * 4;
    int row = i4 / K, col = i4 % K;
    float4 v = ((const float4*)s)[i];
    float vv[4] = {v.x, v.y, v.z, v.w};
    __half h[4], l[4];
#pragma unroll
    for (int j = 0; j < 4; j++) {
        h[j] = __float2half_rn(vv[j]);
        l[j] = __float2half_rn(vv[j] - __half2float(h[j]));
    }
    size_t base = (size_t)row * 2 * K + col;
    *(uint2*)(d + base) = make_uint2(pack_h2(h[0], h[1]), pack_h2(h[2], h[3]));
    *(uint2*)(d + base + K) = make_uint2(pack_h2(l[0], l[1]), pack_h2(l[2], l[3]));
}

// gathered fp32->fp16: row i of dst = row perm[i] of src (256 cols)
__global__ __launch_bounds__(256) void cvt_h_gather(
    const float* __restrict__ s, __half* __restrict__ d)
{
    int tid = blockIdx.x * blockDim.x + threadIdx.x;
    int row = tid >> 6;
    int col = (tid & 63) * 4;
    if (row >= N_EDGES) return;
    int srow = g_perm[row];
    float4 v = *(const float4*)(s + (size_t)srow * DIM + col);
    *(uint2*)(d + (size_t)row * DIM + col) =
        make_uint2(pack_h2(__float2half_rn(v.x), __float2half_rn(v.y)),
                   pack_h2(__float2half_rn(v.z), __float2half_rn(v.w)));
}

// W [K,N] row-major -> out [N, cat*K]; cat=2: [Whi|Whi], cat=1: [Whi]
__global__ void tconv(const float* __restrict__ W, __half* __restrict__ out,
                      int K, int N, int cat)
{
    __shared__ float t[32][33];
    int tx = threadIdx.x, ty = threadIdx.y;
    int n0 = blockIdx.x * 32, k0 = blockIdx.y * 32;
#pragma unroll
    for (int r = 0; r < 4; r++)
        t[ty + 8 * r][tx] = W[(size_t)(k0 + ty + 8 * r) * N + n0 + tx];
    __syncthreads();
    int stride = cat * K;
#pragma unroll
    for (int r = 0; r < 4; r++) {
        int nl = ty + 8 * r;
        float v = t[tx][nl];
        size_t o = (size_t)(n0 + nl) * stride + k0 + tx;
        __half h = __float2half_rn(v);
        out[o] = h;
        if (cat == 2) out[o + K] = h;
    }
}

__global__ void pack_bias(const float* __restrict__ bq, const float* __restrict__ bk,
                          const float* __restrict__ bv, const float* __restrict__ bs)
{
    int b = blockIdx.x, t = threadIdx.x;
    float v = (t < 256) ? bq[b * 256 + t]
            : (t < 512) ? bk[b * 256 + t - 256]
            : (t < 768) ? bv[b * 256 + t - 512]
                        : bs[b * 256 + t - 768];
    g_bqkvs[b * 1024 + t] = v;
}

// ---------------- fused CSR attention + skip + residual + LN reduction ---------
__global__ __launch_bounds__(256) void attn_csr(
    const __half* __restrict__ eh, const float* __restrict__ x,
    float* __restrict__ y, double* __restrict__ red)
{
    int tid = threadIdx.x, lane = tid & 31, wid = tid >> 5;
    int node = blockIdx.x * 8 + wid;

    double ls = 0.0, lq = 0.0;
    if (node < N_NODES) {
        const float* qrow = g_qkvs + (size_t)node * 1024;
        float4 q0 = *(const float4*)(qrow + lane * 8);
        float4 q1 = *(const float4*)(qrow + lane * 8 + 4);

        int start = g_rowstart[node];
        int end   = g_rowstart[node + 1];

        float m0 = 0.f, m1 = 0.f, m2 = 0.f, m3 = 0.f;
        float m4 = 0.f, m5 = 0.f, m6 = 0.f, m7 = 0.f;
        float denom = 0.f;

        for (int j = start; j < end; j++) {
            int src = g_src_s[j];
            float invd = g_invd_s[j];

            const float* krow = g_qkvs + (size_t)src * 1024 + 256;
            const float* vrow = g_qkvs + (size_t)src * 1024 + 512;
            float4 k0 = *(const float4*)(krow + lane * 8);
            float4 k1 = *(const float4*)(krow + lane * 8 + 4);
            int4 evi = *(const int4*)(eh + (size_t)j * DIM + lane * 8);
            __half2* ehp = (__half2*)&evi;
            float2 e0 = __half22float2(ehp[0]), e1 = __half22float2(ehp[1]);
            float2 e2 = __half22float2(ehp[2]), e3 = __half22float2(ehp[3]);

            float p = 0.f;
            p = fmaf(q0.x, k0.x + e0.x, p);
            p = fmaf(q0.y, k0.y + e0.y, p);
            p = fmaf(q0.z, k0.z + e1.x, p);
            p = fmaf(q0.w, k0.w + e1.y, p);
            p = fmaf(q1.x, k1.x + e2.x, p);
            p = fmaf(q1.y, k1.y + e2.y, p);
            p = fmaf(q1.z, k1.z + e3.x, p);
            p = fmaf(q1.w, k1.w + e3.y, p);
            p += __shfl_xor_sync(0xffffffffu, p, 1);
            p += __shfl_xor_sync(0xffffffffu, p, 2);

            float ex = __expf(p * invd * RSQRT_DH);
            denom += ex;

            float4 v0 = *(const float4*)(vrow + lane * 8);
            float4 v1 = *(const float4*)(vrow + lane * 8 + 4);
            m0 = fmaf(v0.x + e0.x, ex, m0);
            m1 = fmaf(v0.y + e0.y, ex, m1);
            m2 = fmaf(v0.z + e1.x, ex, m2);
            m3 = fmaf(v0.w + e1.y, ex, m3);
            m4 = fmaf(v1.x + e2.x, ex, m4);
            m5 = fmaf(v1.y + e2.y, ex, m5);
            m6 = fmaf(v1.z + e3.x, ex, m6);
            m7 = fmaf(v1.w + e3.y, ex, m7);
        }

        float inv = 1.0f / (denom + 1e-16f);
        const float* xr = x + (size_t)node * 256 + lane * 8;
        const float* sk = g_qkvs + (size_t)node * 1024 + 768 + lane * 8;
        float4 xv0 = *(const float4*)(xr);
        float4 xv1 = *(const float4*)(xr + 4);
        float4 sk0 = *(const float4*)(sk);
        float4 sk1 = *(const float4*)(sk + 4);

        float r0 = xv0.x + sk0.x + m0 * inv;
        float r1 = xv0.y + sk0.y + m1 * inv;
        float r2 = xv0.z + sk0.z + m2 * inv;
        float r3 = xv0.w + sk0.w + m3 * inv;
        float r4 = xv1.x + sk1.x + m4 * inv;
        float r5 = xv1.y + sk1.y + m5 * inv;
        float r6 = xv1.z + sk1.z + m6 * inv;
        float r7 = xv1.w + sk1.w + m7 * inv;

        float* yp = y + (size_t)node * 256 + lane * 8;
        *(float4*)(yp)     = make_float4(r0, r1, r2, r3);
        *(float4*)(yp + 4) = make_float4(r4, r5, r6, r7);

        ls = (double)r0 + (double)r1 + (double)r2 + (double)r3 +
             (double)r4 + (double)r5 + (double)r6 + (double)r7;
        lq = (double)r0 * r0 + (double)r1 * r1 + (double)r2 * r2 + (double)r3 * r3 +
             (double)r4 * r4 + (double)r5 * r5 + (double)r6 * r6 + (double)r7 * r7;
    }

#pragma unroll
    for (int o = 16; o > 0; o >>= 1) {
        ls += __shfl_down_sync(0xffffffffu, ls, o);
        lq += __shfl_down_sync(0xffffffffu, lq, o);
    }
    __shared__ double shs[8], shq[8];
    if (lane == 0) { shs[wid] = ls; shq[wid] = lq; }
    __syncthreads();
    if (tid == 0) {
        double ts = 0, tq = 0;
#pragma unroll
        for (int k = 0; k < 8; k++) { ts += shs[k]; tq += shq[k]; }
        atomicAdd(&red[0], ts);
        atomicAdd(&red[1], tq);
    }
}

// ---------------- plain residual + DP reduction --------------------------------
__global__ __launch_bounds__(256) void resred(
    const float* __restrict__ a, const float* __restrict__ b,
    float* __restrict__ y, double* __restrict__ red)
{
    int i = blockIdx.x * blockDim.x + threadIdx.x;
    float4 av = ((const float4*)a)[i];
    float4 bv = ((const float4*)b)[i];
    float4 s = make_float4(av.x + bv.x, av.y + bv.y, av.z + bv.z, av.w + bv.w);
    ((float4*)y)[i] = s;

    double ls = (double)s.x + (double)s.y + (double)s.z + (double)s.w;
    double lq = (double)s.x * s.x + (double)s.y * s.y +
                (double)s.z * s.z + (double)s.w * s.w;
#pragma unroll
    for (int o = 16; o > 0; o >>= 1) {
        ls += __shfl_down_sync(0xffffffffu, ls, o);
        lq += __shfl_down_sync(0xffffffffu, lq, o);
    }
    __shared__ double shs[8], shq[8];
    int wid = threadIdx.x >> 5, lane = threadIdx.x & 31;
    if (lane == 0) { shs[wid] = ls; shq[wid] = lq; }
    __syncthreads();
    if (threadIdx.x == 0) {
        double ts = 0, tq = 0;
#pragma unroll
        for (int k = 0; k < 8; k++) { ts += shs[k]; tq += shq[k]; }
        atomicAdd(&red[0], ts);
        atomicAdd(&red[1], tq);
    }
}

// ---------------- graph layernorm apply + optional 2-cat fp16 emit -------------
__global__ __launch_bounds__(256) void lnapply(
    const float* __restrict__ y, const float* __restrict__ g,
    const float* __restrict__ b, float* __restrict__ o,
    __half* __restrict__ ocat, const double* __restrict__ red)
{
    int i = blockIdx.x * blockDim.x + threadIdx.x;
    double mean = red[0] / (double)LN_CNT;
    double var  = red[1] / (double)LN_CNT - mean * mean;
    if (var < 0) var = 0;
    float inv = 1.0f / ((float)sqrt(var) + LN_EPS);
    float mu = (float)mean;

    int i4 = i * 4;
    int c = i4 % DIM;
    int row = i4 / DIM;
    float4 yv = ((const float4*)y)[i];
    float4 gv = *(const float4*)(g + c);
    float4 bv = *(const float4*)(b + c);
    float4 r;
    r.x = (yv.x - mu) * inv * gv.x + bv.x;
    r.y = (yv.y - mu) * inv * gv.y + bv.y;
    r.z = (yv.z - mu) * inv * gv.z + bv.z;
    r.w = (yv.w - mu) * inv * gv.w + bv.w;
    ((float4*)o)[i] = r;

    if (ocat) {
        float vv[4] = {r.x, r.y, r.z, r.w};
        __half h[4], l[4];
#pragma unroll
        for (int j = 0; j < 4; j++) {
            h[j] = __float2half_rn(vv[j]);
            l[j] = __float2half_rn(vv[j] - __half2float(h[j]));
        }
        size_t base = (size_t)row * 2 * DIM + c;
        *(uint2*)(ocat + base) = make_uint2(pack_h2(h[0], h[1]), pack_h2(h[2], h[3]));
        *(uint2*)(ocat + base + DIM) = make_uint2(pack_h2(l[0], l[1]), pack_h2(l[2], l[3]));
    }
}

// ---------------- host orchestration -------------------------------------------
extern "C" void kernel_launch(void* const* d_in, const int* in_sizes, int n_in,
                              void* d_out, int out_size)
{
    const float* x_in   = (const float*)d_in[0];
    const int*   ei     = (const int*)d_in[1];
    const float* x_edge = (const float*)d_in[2];
    const float* x_dist = (const float*)d_in[3];
    const float* Wq_a   = (const float*)d_in[4];
    const float* bq_a   = (const float*)d_in[5];
    const float* Wk_a   = (const float*)d_in[6];
    const float* bk_a   = (const float*)d_in[7];
    const float* Wv_a   = (const float*)d_in[8];
    const float* bv_a   = (const float*)d_in[9];
    const float* We_a   = (const float*)d_in[10];
    const float* Ws_a   = (const float*)d_in[11];
    const float* bs_a   = (const float*)d_in[12];
    const float* g1_a   = (const float*)d_in[13];
    const float* b1_a   = (const float*)d_in[14];
    const float* W1_a   = (const float*)d_in[15];
    const float* c1_a   = (const float*)d_in[16];
    const float* W2_a   = (const float*)d_in[17];
    const float* c2_a   = (const float*)d_in[18];
    const float* g2_a   = (const float*)d_in[19];
    const float* b2_a   = (const float*)d_in[20];

    static int smem_set = 0;
    if (!smem_set) {
        cudaFuncSetAttribute(gemm_mma, cudaFuncAttributeMaxDynamicSharedMemorySize, NG_SMEM);
        cudaFuncSetAttribute(gemm_mma2, cudaFuncAttributeMaxDynamicSharedMemorySize, NG2_SMEM);
        cudaFuncSetAttribute(gemm_edge, cudaFuncAttributeMaxDynamicSharedMemorySize, EG_SMEM);
        smem_set = 1;
    }

    float *qkvs_, *out_, *y_, *x_, *bqkvs_;
    double* red_;
    __half *eh3_, *xeh_, *xc_, *yc_, *hc_, *wt_;
    cudaGetSymbolAddress((void**)&qkvs_, g_qkvs);
    cudaGetSymbolAddress((void**)&eh3_,  g_e_h3);
    cudaGetSymbolAddress((void**)&out_,  g_out);
    cudaGetSymbolAddress((void**)&y_,    g_y);
    cudaGetSymbolAddress((void**)&x_,    g_x);
    cudaGetSymbolAddress((void**)&red_,  g_red);
    cudaGetSymbolAddress((void**)&bqkvs_, g_bqkvs);
    cudaGetSymbolAddress((void**)&xeh_,  g_xe_h);
    cudaGetSymbolAddress((void**)&xc_,   g_x_cat);
    cudaGetSymbolAddress((void**)&yc_,   g_y_cat);
    cudaGetSymbolAddress((void**)&hc_,   g_h_cat);
    cudaGetSymbolAddress((void**)&wt_,   g_wt_cat);

    const int elem4 = LN_CNT / 4;

    // CSR build (also zeroes the 12 LN accumulators)
    zero_deg<<<(N_NODES + 255) / 256, 256>>>();
    hist_dst<<<(N_EDGES + 255) / 256, 256>>>(ei);
    scan16k<<<1, 1024>>>();
    scatter_perm<<<(N_EDGES + 255) / 256, 256>>>(ei, x_dist);

    // conversions + weight prep
    cvt_cat2<<<(elem4 + 255) / 256, 256>>>(x_in, xc_, DIM, elem4);
    cvt_h_gather<<<(N_EDGES * 64) / 256, 256>>>(x_edge, xeh_);
    pack_bias<<<3, 1024>>>(bq_a, bk_a, bv_a, bs_a);
    dim3 tb(32, 8);
    for (int b = 0; b < 3; b++) {
        size_t wb = (size_t)b * WB;
        __half* wq = wt_ + wb + OW_QKVS;
        tconv<<<dim3(8, 8),  tb>>>(Wq_a + (size_t)b * DIM * DIM, wq,             DIM, DIM, 2);
        tconv<<<dim3(8, 8),  tb>>>(Wk_a + (size_t)b * DIM * DIM, wq + 256 * 512, DIM, DIM, 2);
        tconv<<<dim3(8, 8),  tb>>>(Wv_a + (size_t)b * DIM * DIM, wq + 512 * 512, DIM, DIM, 2);
        tconv<<<dim3(8, 8),  tb>>>(Ws_a + (size_t)b * DIM * DIM, wq + 768 * 512, DIM, DIM, 2);
        tconv<<<dim3(8, 8),  tb>>>(We_a + (size_t)b * DIM * DIM, wt_ + wb + OW_E, DIM, DIM, 1);
        tconv<<<dim3(32, 8), tb>>>(W1_a + (size_t)b * DIM * HID, wt_ + wb + OW_1, DIM, HID, 2);
        tconv<<<dim3(8, 32), tb>>>(W2_a + (size_t)b * HID * DIM, wt_ + wb + OW_2, HID, DIM, 2);
    }

    // edge projections for all blocks, output already CSR-ordered
    gemm_edge<<<N_EDGES / 128, 128, EG_SMEM>>>(xeh_, wt_, eh3_);

    const float* xcur = x_in;
    for (int blk = 0; blk < 3; blk++) {
        size_t wb = (size_t)blk * WB;
        const float* g1 = g1_a + blk * DIM;
        const float* b1 = b1_a + blk * DIM;
        const float* c1 = c1_a + blk * HID;
        const float* c2 = c2_a + blk * DIM;
        const float* g2 = g2_a + blk * DIM;
        const float* b2 = b2_a + blk * DIM;
        double* redb = red_ + blk * 4;

        gemm_mma<<<dim3(8, 125), 128, NG_SMEM>>>(
            xc_, wt_ + wb + OW_QKVS, bqkvs_ + blk * 1024,
            qkvs_, nullptr, N_NODES, 1024, 512, 0);

        attn_csr<<<N_NODES / 8, 256>>>(eh3_ + (size_t)blk * N_EDGES * DIM,
                                       xcur, y_, redb + 0);
        lnapply<<<elem4 / 256, 256>>>(y_, g1, b1, y_, yc_, redb + 0);

        gemm_mma<<<dim3(8, 125), 128, NG_SMEM>>>(
            yc_, wt_ + wb + OW_1, c1, nullptr, hc_, N_NODES, HID, 512, 1);
        gemm_mma2<<<dim3(1, 125), 256, NG2_SMEM>>>(
            hc_, wt_ + wb + OW_2, c2, out_, N_NODES, DIM, 2048);

        resred<<<elem4 / 256, 256>>>(y_, out_, out_, redb + 2);
        float* xdst = (blk == 2) ? (float*)d_out : x_;
        __half* xcat = (blk == 2) ? nullptr : xc_;
        lnapply<<<elem4 / 256, 256>>>(out_, g2, b2, xdst, xcat, redb + 2);

        xcur = x_;
    }
}

// round 15
// speedup vs baseline: 1.5332x; 1.0088x over previous
#include <cuda_runtime.h>
#include <cuda_fp16.h>
#include <math.h>
#include <stdint.h>

#define N_NODES 16000
#define N_EDGES 256000
#define DIM 256
#define HEADS 8
#define HID 1024
#define LN_CNT (N_NODES * DIM)
#define LN_EPS 1e-5f
#define RSQRT_DH 0.17677669529663687f

// cat-weight table offsets (halves, per transformer block)
#define OW_QKVS 0              // [1024, 512]
#define OW_E    524288         // [256, 256]
#define OW_1    589824         // [1024, 512]
#define OW_2    1114112        // [256, 2048]
#define WB      1638400

// ---------------- scratch -----------------------------------------------------
__device__ float    g_q[(size_t)N_NODES * 256];
__device__ float    g_skip[(size_t)N_NODES * 256];
__device__ __half   g_kv[(size_t)N_NODES * 512];         // [k(256) | v(256)] fp16
__device__ __half   g_e_h3[3 * (size_t)N_EDGES * DIM];   // CSR-ordered
__device__ float    g_out[N_NODES * DIM];
__device__ float    g_y[N_NODES * DIM];
__device__ float    g_x[N_NODES * DIM];
__device__ double   g_red[12];
__device__ float    g_bqkvs[3 * 1024];
__device__ __half   g_xe_h[(size_t)N_EDGES * DIM];       // CSR-ordered gather
__device__ __half   g_x_cat[(size_t)N_NODES * 2 * DIM];
__device__ __half   g_y_cat[(size_t)N_NODES * 2 * DIM];
__device__ __half   g_h_cat[(size_t)N_NODES * 2 * HID];
__device__ __half   g_wt_cat[3 * WB];
// CSR
__device__ int      g_rowstart[N_NODES + 1];
__device__ int      g_cursor[N_NODES];
__device__ int      g_perm[N_EDGES];
__device__ int      g_src_s[N_EDGES];
__device__ float    g_invd_s[N_EDGES];

// ---------------- helpers -----------------------------------------------------
__device__ __forceinline__ uint32_t smem_u32(const void* p) {
    uint32_t a;
    asm("{ .reg .u64 t; cvta.to.shared.u64 t, %1; cvt.u32.u64 %0, t; }"
        : "=r"(a) : "l"(p));
    return a;
}
__device__ __forceinline__ uint32_t pack_h2(__half a, __half b) {
    __half2 h2 = __halves2half2(a, b);
    return *(uint32_t*)&h2;
}
__device__ __forceinline__ void cp16(uint32_t dst, const void* src) {
    asm volatile("cp.async.cg.shared.global [%0], [%1], 16;"
                 :: "r"(dst), "l"(src) : "memory");
}
__device__ __forceinline__ void ldsm_x4(uint32_t* r, uint32_t addr) {
    asm volatile("ldmatrix.sync.aligned.m8n8.x4.shared.b16 {%0,%1,%2,%3}, [%4];"
                 : "=r"(r[0]), "=r"(r[1]), "=r"(r[2]), "=r"(r[3]) : "r"(addr));
}
__device__ __forceinline__ void mma16816(float* c, const uint32_t* a, uint32_t b0, uint32_t b1) {
    asm volatile(
        "mma.sync.aligned.m16n8k16.row.col.f32.f16.f16.f32 "
        "{%0,%1,%2,%3}, {%4,%5,%6,%7}, {%8,%9}, {%0,%1,%2,%3};"
        : "+f"(c[0]), "+f"(c[1]), "+f"(c[2]), "+f"(c[3])
        : "r"(a[0]), "r"(a[1]), "r"(a[2]), "r"(a[3]), "r"(b0), "r"(b1));
}

// qkvs split write: col<256 -> q fp32; [256,512) -> k fp16; [512,768) -> v fp16;
// [768,1024) -> skip fp32
__device__ __forceinline__ void qkvs_emit(int row, int col, float a, float b) {
    if (col < 256) {
        *(float2*)(g_q + (size_t)row * 256 + col) = make_float2(a, b);
    } else if (col < 512) {
        *(__half2*)(g_kv + (size_t)row * 512 + (col - 256)) = __floats2half2_rn(a, b);
    } else if (col < 768) {
        *(__half2*)(g_kv + (size_t)row * 512 + 256 + (col - 512)) = __floats2half2_rn(a, b);
    } else {
        *(float2*)(g_skip + (size_t)row * 256 + (col - 768)) = make_float2(a, b);
    }
}

// ================== node GEMM 128x128 (4 warps, 3-stage) ======================
#define NG_SMEM 98304

__device__ __forceinline__ void load_chunk_n(
    uint32_t st, const __half* __restrict__ A, const __half* __restrict__ B,
    size_t rowA0, size_t rowB0, int K3, int k0, int tid)
{
#pragma unroll
    for (int i = 0; i < 8; i++) {
        int u = tid + (i << 7);
        int row = u >> 3, kk = u & 7;
        uint32_t off = (uint32_t)(row * 128 + kk * 16);
        uint32_t sw = off ^ ((off >> 3) & 0x70);
        cp16(st + sw, A + (rowA0 + row) * (size_t)K3 + k0 + kk * 8);
        cp16(st + 16384 + sw, B + (rowB0 + row) * (size_t)K3 + k0 + kk * 8);
    }
}

__global__ __launch_bounds__(128) void gemm_mma(
    const __half* __restrict__ A, const __half* __restrict__ B,
    const float* __restrict__ bias,
    __half* __restrict__ Ccat,
    int M, int N, int K3, int relu, int mode)   // mode 1 = Ccat 2-cat, 2 = qkvs split
{
    extern __shared__ __align__(128) char smem[];
    uint32_t sbase = smem_u32(smem);

    int tid = threadIdx.x, lane = tid & 31, wid = tid >> 5;
    int warpM = wid >> 1, warpN = wid & 1;
    int tN = blockIdx.x, tM = blockIdx.y;
    size_t rowA0 = (size_t)tM * 128;
    size_t rowB0 = (size_t)tN * 128;
    int nch = K3 >> 6;

    float acc[4][8][4];
#pragma unroll
    for (int i = 0; i < 4; i++)
#pragma unroll
        for (int j = 0; j < 8; j++)
#pragma unroll
            for (int t = 0; t < 4; t++) acc[i][j][t] = 0.f;

    load_chunk_n(sbase, A, B, rowA0, rowB0, K3, 0, tid);
    asm volatile("cp.async.commit_group;" ::: "memory");
    load_chunk_n(sbase + 32768, A, B, rowA0, rowB0, K3, 64, tid);
    asm volatile("cp.async.commit_group;" ::: "memory");

    for (int c = 0; c < nch; c++) {
        if (c + 2 < nch) {
            uint32_t sb = sbase + (uint32_t)((c + 2) % 3) * 32768u;
            load_chunk_n(sb, A, B, rowA0, rowB0, K3, (c + 2) << 6, tid);
            asm volatile("cp.async.commit_group;" ::: "memory");
            asm volatile("cp.async.wait_group 2;" ::: "memory");
        } else if (c + 1 < nch) {
            asm volatile("cp.async.wait_group 1;" ::: "memory");
        } else {
            asm volatile("cp.async.wait_group 0;" ::: "memory");
        }
        __syncthreads();

        uint32_t aB = sbase + (uint32_t)(c % 3) * 32768u;
        uint32_t bB = aB + 16384;
#pragma unroll
        for (int ks = 0; ks < 4; ks++) {
            uint32_t af[4][4], bf[4][4];
#pragma unroll
            for (int mf = 0; mf < 4; mf++) {
                int row = warpM * 64 + mf * 16 + (lane & 15);
                uint32_t off = (uint32_t)(row * 128 + ks * 32 + ((lane >> 4) << 4));
                off ^= (off >> 3) & 0x70;
                ldsm_x4(af[mf], aB + off);
            }
#pragma unroll
            for (int nf2 = 0; nf2 < 4; nf2++) {
                int row = warpN * 64 + nf2 * 16 + (lane & 15);
                uint32_t off = (uint32_t)(row * 128 + ks * 32 + ((lane >> 4) << 4));
                off ^= (off >> 3) & 0x70;
                ldsm_x4(bf[nf2], bB + off);
            }
#pragma unroll
            for (int mf = 0; mf < 4; mf++)
#pragma unroll
                for (int nf2 = 0; nf2 < 4; nf2++) {
                    mma16816(acc[mf][nf2 * 2],     af[mf], bf[nf2][0], bf[nf2][2]);
                    mma16816(acc[mf][nf2 * 2 + 1], af[mf], bf[nf2][1], bf[nf2][3]);
                }
        }
        __syncthreads();
    }

    int m0 = tM * 128 + warpM * 64;
    int n0 = tN * 128 + warpN * 64;
#pragma unroll
    for (int mf = 0; mf < 4; mf++) {
#pragma unroll
        for (int nf = 0; nf < 8; nf++) {
            int r = m0 + mf * 16 + (lane >> 2);
            int col = n0 + nf * 8 + ((lane & 3) << 1);
            float b0 = bias ? __ldg(bias + col) : 0.f;
            float b1 = bias ? __ldg(bias + col + 1) : 0.f;
            float v00 = acc[mf][nf][0] + b0, v01 = acc[mf][nf][1] + b1;
            float v10 = acc[mf][nf][2] + b0, v11 = acc[mf][nf][3] + b1;
            if (relu) {
                v00 = fmaxf(v00, 0.f); v01 = fmaxf(v01, 0.f);
                v10 = fmaxf(v10, 0.f); v11 = fmaxf(v11, 0.f);
            }
            if (mode == 2) {
                qkvs_emit(r, col, v00, v01);
                qkvs_emit(r + 8, col, v10, v11);
            } else {   // mode 1: 2-cat [hi|lo]
                __half h00 = __float2half_rn(v00), h01 = __float2half_rn(v01);
                __half h10 = __float2half_rn(v10), h11 = __float2half_rn(v11);
                uint32_t uh0 = pack_h2(h00, h01), uh1 = pack_h2(h10, h11);
                uint32_t ul0 = pack_h2(__float2half_rn(v00 - __half2float(h00)),
                                       __float2half_rn(v01 - __half2float(h01)));
                uint32_t ul1 = pack_h2(__float2half_rn(v10 - __half2float(h10)),
                                       __float2half_rn(v11 - __half2float(h11)));
                size_t b0a = (size_t)r * 2 * N + col;
                size_t b1a = (size_t)(r + 8) * 2 * N + col;
                *(uint32_t*)(Ccat + b0a) = uh0;
                *(uint32_t*)(Ccat + b0a + N) = ul0;
                *(uint32_t*)(Ccat + b1a) = uh1;
                *(uint32_t*)(Ccat + b1a + N) = ul1;
            }
        }
    }
}

// ====== node GEMM 128x256 (8 warps, 2-stage) — FFN2 + residual + LN red ======
#define NG2_SMEM 98304

__device__ __forceinline__ void load_chunk_n2(
    uint32_t st, const __half* __restrict__ A, const __half* __restrict__ B,
    size_t rowA0, size_t rowB0, int K3, int k0, int tid)
{
#pragma unroll
    for (int i = 0; i < 4; i++) {
        int u = tid + (i << 8);
        int row = u >> 3, kk = u & 7;
        uint32_t off = (uint32_t)(row * 128 + kk * 16);
        uint32_t sw = off ^ ((off >> 3) & 0x70);
        cp16(st + sw, A + (rowA0 + row) * (size_t)K3 + k0 + kk * 8);
    }
#pragma unroll
    for (int i = 0; i < 8; i++) {
        int u = tid + (i << 8);
        int row = u >> 3, kk = u & 7;
        uint32_t off = (uint32_t)(row * 128 + kk * 16);
        uint32_t sw = off ^ ((off >> 3) & 0x70);
        cp16(st + 16384 + sw, B + (rowB0 + row) * (size_t)K3 + k0 + kk * 8);
    }
}

__global__ __launch_bounds__(256) void gemm_mma2(
    const __half* __restrict__ A, const __half* __restrict__ B,
    const float* __restrict__ bias, const float* __restrict__ Y,
    float* __restrict__ Cf, double* __restrict__ red,
    int M, int N, int K3)
{
    extern __shared__ __align__(128) char smem[];
    uint32_t sbase = smem_u32(smem);

    int tid = threadIdx.x, lane = tid & 31, wid = tid >> 5;
    int warpM = wid >> 2, warpN = wid & 3;
    int tN = blockIdx.x, tM = blockIdx.y;
    size_t rowA0 = (size_t)tM * 128;
    size_t rowB0 = (size_t)tN * 256;
    int nch = K3 >> 6;

    float acc[4][8][4];
#pragma unroll
    for (int i = 0; i < 4; i++)
#pragma unroll
        for (int j = 0; j < 8; j++)
#pragma unroll
            for (int t = 0; t < 4; t++) acc[i][j][t] = 0.f;

    load_chunk_n2(sbase, A, B, rowA0, rowB0, K3, 0, tid);
    asm volatile("cp.async.commit_group;" ::: "memory");

    for (int c = 0; c < nch; c++) {
        if (c + 1 < nch) {
            uint32_t sb = sbase + (uint32_t)((c + 1) & 1) * 49152u;
            load_chunk_n2(sb, A, B, rowA0, rowB0, K3, (c + 1) << 6, tid);
            asm volatile("cp.async.commit_group;" ::: "memory");
            asm volatile("cp.async.wait_group 1;" ::: "memory");
        } else {
            asm volatile("cp.async.wait_group 0;" ::: "memory");
        }
        __syncthreads();

        uint32_t aB = sbase + (uint32_t)(c & 1) * 49152u;
        uint32_t bB = aB + 16384;
#pragma unroll
        for (int ks = 0; ks < 4; ks++) {
            uint32_t af[4][4], bf[4][4];
#pragma unroll
            for (int mf = 0; mf < 4; mf++) {
                int row = warpM * 64 + mf * 16 + (lane & 15);
                uint32_t off = (uint32_t)(row * 128 + ks * 32 + ((lane >> 4) << 4));
                off ^= (off >> 3) & 0x70;
                ldsm_x4(af[mf], aB + off);
            }
#pragma unroll
            for (int nf2 = 0; nf2 < 4; nf2++) {
                int row = warpN * 64 + nf2 * 16 + (lane & 15);
                uint32_t off = (uint32_t)(row * 128 + ks * 32 + ((lane >> 4) << 4));
                off ^= (off >> 3) & 0x70;
                ldsm_x4(bf[nf2], bB + off);
            }
#pragma unroll
            for (int mf = 0; mf < 4; mf++)
#pragma unroll
                for (int nf2 = 0; nf2 < 4; nf2++) {
                    mma16816(acc[mf][nf2 * 2],     af[mf], bf[nf2][0], bf[nf2][2]);
                    mma16816(acc[mf][nf2 * 2 + 1], af[mf], bf[nf2][1], bf[nf2][3]);
                }
        }
        __syncthreads();
    }

    // epilogue: s = acc + bias + y; write; accumulate DP sum/sumsq
    int m0 = tM * 128 + warpM * 64;
    int n0 = tN * 256 + warpN * 64;
    double ls = 0.0, lq = 0.0;
#pragma unroll
    for (int mf = 0; mf < 4; mf++) {
#pragma unroll
        for (int nf = 0; nf < 8; nf++) {
            int r = m0 + mf * 16 + (lane >> 2);
            int col = n0 + nf * 8 + ((lane & 3) << 1);
            float b0 = bias ? __ldg(bias + col) : 0.f;
            float b1 = bias ? __ldg(bias + col + 1) : 0.f;
            float2 y0 = *(const float2*)(Y + (size_t)r * N + col);
            float2 y1 = *(const float2*)(Y + (size_t)(r + 8) * N + col);
            float s00 = acc[mf][nf][0] + b0 + y0.x;
            float s01 = acc[mf][nf][1] + b1 + y0.y;
            float s10 = acc[mf][nf][2] + b0 + y1.x;
            float s11 = acc[mf][nf][3] + b1 + y1.y;
            *(float2*)(Cf + (size_t)r * N + col) = make_float2(s00, s01);
            *(float2*)(Cf + (size_t)(r + 8) * N + col) = make_float2(s10, s11);
            ls += (double)s00 + (double)s01 + (double)s10 + (double)s11;
            lq += (double)s00 * s00 + (double)s01 * s01 +
                  (double)s10 * s10 + (double)s11 * s11;
        }
    }
#pragma unroll
    for (int o = 16; o > 0; o >>= 1) {
        ls += __shfl_down_sync(0xffffffffu, ls, o);
        lq += __shfl_down_sync(0xffffffffu, lq, o);
    }
    __shared__ double shs[8], shq[8];
    if (lane == 0) { shs[wid] = ls; shq[wid] = lq; }
    __syncthreads();
    if (tid == 0) {
        double ts = 0, tq = 0;
#pragma unroll
        for (int k = 0; k < 8; k++) { ts += shs[k]; tq += shq[k]; }
        atomicAdd(&red[0], ts);
        atomicAdd(&red[1], tq);
    }
}

// ================== edge GEMM: A-resident, all 3 blocks (1-cat) ===============
#define EG_SMEM 98304

__global__ __launch_bounds__(128) void gemm_edge(
    const __half* __restrict__ XE, const __half* __restrict__ WT,
    __half* __restrict__ EH)
{
    extern __shared__ __align__(128) char smem[];
    uint32_t sbase = smem_u32(smem);
    uint32_t bbase = sbase + 65536;

    int tid = threadIdx.x, lane = tid & 31, wid = tid >> 5;
    int warpM = wid >> 1, warpN = wid & 1;
    size_t rowA0 = (size_t)blockIdx.x * 128;

#pragma unroll
    for (int ch = 0; ch < 4; ch++) {
#pragma unroll
        for (int i = 0; i < 8; i++) {
            int u = tid + (i << 7);
            int row = u >> 3, kk = u & 7;
            uint32_t off = (uint32_t)(row * 128 + kk * 16);
            uint32_t sw = off ^ ((off >> 3) & 0x70);
            cp16(sbase + ch * 16384 + sw, XE + (rowA0 + row) * 256 + ch * 64 + kk * 8);
        }
    }
    {
#pragma unroll
        for (int i = 0; i < 8; i++) {
            int u = tid + (i << 7);
            int row = u >> 3, kk = u & 7;
            uint32_t off = (uint32_t)(row * 128 + kk * 16);
            uint32_t sw = off ^ ((off >> 3) & 0x70);
            cp16(bbase + sw, WT + OW_E + (size_t)row * 256 + kk * 8);
        }
    }
    asm volatile("cp.async.commit_group;" ::: "memory");

    float acc[4][8][4];
#pragma unroll
    for (int i = 0; i < 4; i++)
#pragma unroll
        for (int j = 0; j < 8; j++)
#pragma unroll
            for (int t = 0; t < 4; t++) acc[i][j][t] = 0.f;

    for (int it = 0; it < 24; it++) {
        if (it < 23) {
            int j = it + 1;
            int wt = j >> 2, ck = j & 3;
            int blkj = wt >> 1, nh = wt & 1;
            const __half* Bp = WT + (size_t)blkj * WB + OW_E;
            uint32_t bb = bbase + (uint32_t)(j & 1) * 16384u;
#pragma unroll
            for (int i = 0; i < 8; i++) {
                int u = tid + (i << 7);
                int row = u >> 3, kk = u & 7;
                uint32_t off = (uint32_t)(row * 128 + kk * 16);
                uint32_t sw = off ^ ((off >> 3) & 0x70);
                cp16(bb + sw, Bp + (size_t)(nh * 128 + row) * 256 + ck * 64 + kk * 8);
            }
            asm volatile("cp.async.commit_group;" ::: "memory");
            asm volatile("cp.async.wait_group 1;" ::: "memory");
        } else {
            asm volatile("cp.async.wait_group 0;" ::: "memory");
        }
        __syncthreads();

        int ck = it & 3;
        uint32_t aB = sbase + (uint32_t)ck * 16384u;
        uint32_t bB = bbase + (uint32_t)(it & 1) * 16384u;
#pragma unroll
        for (int ks = 0; ks < 4; ks++) {
            uint32_t af[4][4], bf[4][4];
#pragma unroll
            for (int mf = 0; mf < 4; mf++) {
                int row = warpM * 64 + mf * 16 + (lane & 15);
                uint32_t off = (uint32_t)(row * 128 + ks * 32 + ((lane >> 4) << 4));
                off ^= (off >> 3) & 0x70;
                ldsm_x4(af[mf], aB + off);
            }
#pragma unroll
            for (int nf2 = 0; nf2 < 4; nf2++) {
                int row = warpN * 64 + nf2 * 16 + (lane & 15);
                uint32_t off = (uint32_t)(row * 128 + ks * 32 + ((lane >> 4) << 4));
                off ^= (off >> 3) & 0x70;
                ldsm_x4(bf[nf2], bB + off);
            }
#pragma unroll
            for (int mf = 0; mf < 4; mf++)
#pragma unroll
                for (int nf2 = 0; nf2 < 4; nf2++) {
                    mma16816(acc[mf][nf2 * 2],     af[mf], bf[nf2][0], bf[nf2][2]);
                    mma16816(acc[mf][nf2 * 2 + 1], af[mf], bf[nf2][1], bf[nf2][3]);
                }
        }
        __syncthreads();

        if (ck == 3) {
            int wt = it >> 2;
            int blk = wt >> 1, nh = wt & 1;
            __half* out = EH + (size_t)blk * N_EDGES * DIM;
#pragma unroll
            for (int mf = 0; mf < 4; mf++) {
#pragma unroll
                for (int nf = 0; nf < 8; nf++) {
                    int r = (int)rowA0 + warpM * 64 + mf * 16 + (lane >> 2);
                    int col = nh * 128 + warpN * 64 + nf * 8 + ((lane & 3) << 1);
                    *(__half2*)(out + (size_t)r * DIM + col) =
                        __floats2half2_rn(acc[mf][nf][0], acc[mf][nf][1]);
                    *(__half2*)(out + (size_t)(r + 8) * DIM + col) =
                        __floats2half2_rn(acc[mf][nf][2], acc[mf][nf][3]);
#pragma unroll
                    for (int t = 0; t < 4; t++) acc[mf][nf][t] = 0.f;
                }
            }
        }
    }
}

// ---------------- CSR build ----------------------------------------------------
__global__ void zero_deg() {
    int i = blockIdx.x * blockDim.x + threadIdx.x;
    if (i < N_NODES) g_cursor[i] = 0;
    if (i < 12) g_red[i] = 0.0;
}
__global__ void hist_dst(const int* __restrict__ ei) {
    int i = blockIdx.x * blockDim.x + threadIdx.x;
    if (i < N_EDGES) atomicAdd(&g_cursor[ei[N_EDGES + i]], 1);
}
__global__ __launch_bounds__(1024) void scan16k() {
    __shared__ int warp_tot[32];
    int tid = threadIdx.x, lane = tid & 31, wid = tid >> 5;
    int base = tid * 16;
    int vals[16];
    int s = 0;
#pragma unroll
    for (int t = 0; t < 16; t++) {
        int idx = base + t;
        int v = (idx < N_NODES) ? g_cursor[idx] : 0;
        vals[t] = s;
        s += v;
    }
    int x = s;
#pragma unroll
    for (int o = 1; o < 32; o <<= 1) {
        int n = __shfl_up_sync(0xffffffffu, x, o);
        if (lane >= o) x += n;
    }
    if (lane == 31) warp_tot[wid] = x;
    __syncthreads();
    if (wid == 0) {
        int t = warp_tot[lane];
        int y = t;
#pragma unroll
        for (int o = 1; o < 32; o <<= 1) {
            int n = __shfl_up_sync(0xffffffffu, y, o);
            if (lane >= o) y += n;
        }
        warp_tot[lane] = y - t;
    }
    __syncthreads();
    int offset = warp_tot[wid] + (x - s);
#pragma unroll
    for (int t = 0; t < 16; t++) {
        int idx = base + t;
        if (idx < N_NODES) g_rowstart[idx] = offset + vals[t];
    }
    if (tid == 1023) g_rowstart[N_NODES] = offset + s;
    __syncthreads();
#pragma unroll
    for (int t = 0; t < 16; t++) {
        int idx = base + t;
        if (idx < N_NODES) g_cursor[idx] = g_rowstart[idx];
    }
}
__global__ void scatter_perm(const int* __restrict__ ei,
                             const float* __restrict__ xdist) {
    int i = blockIdx.x * blockDim.x + threadIdx.x;
    if (i < N_EDGES) {
        int d = ei[N_EDGES + i];
        int pos = atomicAdd(&g_cursor[d], 1);
        g_perm[pos] = i;
        g_src_s[pos] = ei[i];
        g_invd_s[pos] = 1.0f / xdist[i];
    }
}

// ---------------- converters / weight prep -------------------------------------
__global__ __launch_bounds__(256) void cvt_cat2(
    const float* __restrict__ s, __half* __restrict__ d, int K, int n4)
{
    int i = blockIdx.x * blockDim.x + threadIdx.x;
    if (i >= n4) return;
    int i4 = i * 4;
    int row = i4 / K, col = i4 % K;
    float4 v = ((const float4*)s)[i];
    float vv[4] = {v.x, v.y, v.z, v.w};
    __half h[4], l[4];
#pragma unroll
    for (int j = 0; j < 4; j++) {
        h[j] = __float2half_rn(vv[j]);
        l[j] = __float2half_rn(vv[j] - __half2float(h[j]));
    }
    size_t base = (size_t)row * 2 * K + col;
    *(uint2*)(d + base) = make_uint2(pack_h2(h[0], h[1]), pack_h2(h[2], h[3]));
    *(uint2*)(d + base + K) = make_uint2(pack_h2(l[0], l[1]), pack_h2(l[2], l[3]));
}

// gathered fp32->fp16: row i of dst = row perm[i] of src (256 cols)
__global__ __launch_bounds__(256) void cvt_h_gather(
    const float* __restrict__ s, __half* __restrict__ d)
{
    int tid = blockIdx.x * blockDim.x + threadIdx.x;
    int row = tid >> 6;
    int col = (tid & 63) * 4;
    if (row >= N_EDGES) return;
    int srow = g_perm[row];
    float4 v = *(const float4*)(s + (size_t)srow * DIM + col);
    *(uint2*)(d + (size_t)row * DIM + col) =
        make_uint2(pack_h2(__float2half_rn(v.x), __float2half_rn(v.y)),
                   pack_h2(__float2half_rn(v.z), __float2half_rn(v.w)));
}

// W [K,N] row-major -> out [N, cat*K]; cat=2: [Whi|Whi], cat=1: [Whi]
__global__ void tconv(const float* __restrict__ W, __half* __restrict__ out,
                      int K, int N, int cat)
{
    __shared__ float t[32][33];
    int tx = threadIdx.x, ty = threadIdx.y;
    int n0 = blockIdx.x * 32, k0 = blockIdx.y * 32;
#pragma unroll
    for (int r = 0; r < 4; r++)
        t[ty + 8 * r][tx] = W[(size_t)(k0 + ty + 8 * r) * N + n0 + tx];
    __syncthreads();
    int stride = cat * K;
#pragma unroll
    for (int r = 0; r < 4; r++) {
        int nl = ty + 8 * r;
        float v = t[tx][nl];
        size_t o = (size_t)(n0 + nl) * stride + k0 + tx;
        __half h = __float2half_rn(v);
        out[o] = h;
        if (cat == 2) out[o + K] = h;
    }
}

__global__ void pack_bias(const float* __restrict__ bq, const float* __restrict__ bk,
                          const float* __restrict__ bv, const float* __restrict__ bs)
{
    int b = blockIdx.x, t = threadIdx.x;
    float v = (t < 256) ? bq[b * 256 + t]
            : (t < 512) ? bk[b * 256 + t - 256]
            : (t < 768) ? bv[b * 256 + t - 512]
                        : bs[b * 256 + t - 768];
    g_bqkvs[b * 1024 + t] = v;
}

// ---------------- fused CSR attention + skip + residual + LN reduction ---------
__global__ __launch_bounds__(256) void attn_csr(
    const __half* __restrict__ eh, const float* __restrict__ x,
    float* __restrict__ y, double* __restrict__ red)
{
    int tid = threadIdx.x, lane = tid & 31, wid = tid >> 5;
    int node = blockIdx.x * 8 + wid;

    double ls = 0.0, lq = 0.0;
    if (node < N_NODES) {
        const float* qrow = g_q + (size_t)node * 256;
        float4 q0 = *(const float4*)(qrow + lane * 8);
        float4 q1 = *(const float4*)(qrow + lane * 8 + 4);

        int start = g_rowstart[node];
        int end   = g_rowstart[node + 1];

        float m0 = 0.f, m1 = 0.f, m2 = 0.f, m3 = 0.f;
        float m4 = 0.f, m5 = 0.f, m6 = 0.f, m7 = 0.f;
        float denom = 0.f;

        for (int j = start; j < end; j++) {
            int src = g_src_s[j];
            float invd = g_invd_s[j];

            const __half* kvrow = g_kv + (size_t)src * 512;
            int4 kvi = *(const int4*)(kvrow + lane * 8);
            int4 vvi = *(const int4*)(kvrow + 256 + lane * 8);
            int4 evi = *(const int4*)(eh + (size_t)j * DIM + lane * 8);
            __half2* kp = (__half2*)&kvi;
            __half2* vp = (__half2*)&vvi;
            __half2* ep = (__half2*)&evi;
            float2 k0 = __half22float2(kp[0]), k1 = __half22float2(kp[1]);
            float2 k2 = __half22float2(kp[2]), k3 = __half22float2(kp[3]);
            float2 e0 = __half22float2(ep[0]), e1 = __half22float2(ep[1]);
            float2 e2 = __half22float2(ep[2]), e3 = __half22float2(ep[3]);

            float p = 0.f;
            p = fmaf(q0.x, k0.x + e0.x, p);
            p = fmaf(q0.y, k0.y + e0.y, p);
            p = fmaf(q0.z, k1.x + e1.x, p);
            p = fmaf(q0.w, k1.y + e1.y, p);
            p = fmaf(q1.x, k2.x + e2.x, p);
            p = fmaf(q1.y, k2.y + e2.y, p);
            p = fmaf(q1.z, k3.x + e3.x, p);
            p = fmaf(q1.w, k3.y + e3.y, p);
            p += __shfl_xor_sync(0xffffffffu, p, 1);
            p += __shfl_xor_sync(0xffffffffu, p, 2);

            float ex = __expf(p * invd * RSQRT_DH);
            denom += ex;

            float2 v0 = __half22float2(vp[0]), v1 = __half22float2(vp[1]);
            float2 v2 = __half22float2(vp[2]), v3 = __half22float2(vp[3]);
            m0 = fmaf(v0.x + e0.x, ex, m0);
            m1 = fmaf(v0.y + e0.y, ex, m1);
            m2 = fmaf(v1.x + e1.x, ex, m2);
            m3 = fmaf(v1.y + e1.y, ex, m3);
            m4 = fmaf(v2.x + e2.x, ex, m4);
            m5 = fmaf(v2.y + e2.y, ex, m5);
            m6 = fmaf(v3.x + e3.x, ex, m6);
            m7 = fmaf(v3.y + e3.y, ex, m7);
        }

        float inv = 1.0f / (denom + 1e-16f);
        const float* xr = x + (size_t)node * 256 + lane * 8;
        const float* sk = g_skip + (size_t)node * 256 + lane * 8;
        float4 xv0 = *(const float4*)(xr);
        float4 xv1 = *(const float4*)(xr + 4);
        float4 sk0 = *(const float4*)(sk);
        float4 sk1 = *(const float4*)(sk + 4);

        float r0 = xv0.x + sk0.x + m0 * inv;
        float r1 = xv0.y + sk0.y + m1 * inv;
        float r2 = xv0.z + sk0.z + m2 * inv;
        float r3 = xv0.w + sk0.w + m3 * inv;
        float r4 = xv1.x + sk1.x + m4 * inv;
        float r5 = xv1.y + sk1.y + m5 * inv;
        float r6 = xv1.z + sk1.z + m6 * inv;
        float r7 = xv1.w + sk1.w + m7 * inv;

        float* yp = y + (size_t)node * 256 + lane * 8;
        *(float4*)(yp)     = make_float4(r0, r1, r2, r3);
        *(float4*)(yp + 4) = make_float4(r4, r5, r6, r7);

        ls = (double)r0 + (double)r1 + (double)r2 + (double)r3 +
             (double)r4 + (double)r5 + (double)r6 + (double)r7;
        lq = (double)r0 * r0 + (double)r1 * r1 + (double)r2 * r2 + (double)r3 * r3 +
             (double)r4 * r4 + (double)r5 * r5 + (double)r6 * r6 + (double)r7 * r7;
    }

#pragma unroll
    for (int o = 16; o > 0; o >>= 1) {
        ls += __shfl_down_sync(0xffffffffu, ls, o);
        lq += __shfl_down_sync(0xffffffffu, lq, o);
    }
    __shared__ double shs[8], shq[8];
    if (lane == 0) { shs[wid] = ls; shq[wid] = lq; }
    __syncthreads();
    if (tid == 0) {
        double ts = 0, tq = 0;
#pragma unroll
        for (int k = 0; k < 8; k++) { ts += shs[k]; tq += shq[k]; }
        atomicAdd(&red[0], ts);
        atomicAdd(&red[1], tq);
    }
}

// ---------------- graph layernorm apply + optional 2-cat fp16 emit -------------
__global__ __launch_bounds__(256) void lnapply(
    const float* __restrict__ y, const float* __restrict__ g,
    const float* __restrict__ b, float* __restrict__ o,
    __half* __restrict__ ocat, const double* __restrict__ red)
{
    int i = blockIdx.x * blockDim.x + threadIdx.x;
    double mean = red[0] / (double)LN_CNT;
    double var  = red[1] / (double)LN_CNT - mean * mean;
    if (var < 0) var = 0;
    float inv = 1.0f / ((float)sqrt(var) + LN_EPS);
    float mu = (float)mean;

    int i4 = i * 4;
    int c = i4 % DIM;
    int row = i4 / DIM;
    float4 yv = ((const float4*)y)[i];
    float4 gv = *(const float4*)(g + c);
    float4 bv = *(const float4*)(b + c);
    float4 r;
    r.x = (yv.x - mu) * inv * gv.x + bv.x;
    r.y = (yv.y - mu) * inv * gv.y + bv.y;
    r.z = (yv.z - mu) * inv * gv.z + bv.z;
    r.w = (yv.w - mu) * inv * gv.w + bv.w;
    ((float4*)o)[i] = r;

    if (ocat) {
        float vv[4] = {r.x, r.y, r.z, r.w};
        __half h[4], l[4];
#pragma unroll
        for (int j = 0; j < 4; j++) {
            h[j] = __float2half_rn(vv[j]);
            l[j] = __float2half_rn(vv[j] - __half2float(h[j]));
        }
        size_t base = (size_t)row * 2 * DIM + c;
        *(uint2*)(ocat + base) = make_uint2(pack_h2(h[0], h[1]), pack_h2(h[2], h[3]));
        *(uint2*)(ocat + base + DIM) = make_uint2(pack_h2(l[0], l[1]), pack_h2(l[2], l[3]));
    }
}

// ---------------- host orchestration -------------------------------------------
extern "C" void kernel_launch(void* const* d_in, const int* in_sizes, int n_in,
                              void* d_out, int out_size)
{
    const float* x_in   = (const float*)d_in[0];
    const int*   ei     = (const int*)d_in[1];
    const float* x_edge = (const float*)d_in[2];
    const float* x_dist = (const float*)d_in[3];
    const float* Wq_a   = (const float*)d_in[4];
    const float* bq_a   = (const float*)d_in[5];
    const float* Wk_a   = (const float*)d_in[6];
    const float* bk_a   = (const float*)d_in[7];
    const float* Wv_a   = (const float*)d_in[8];
    const float* bv_a   = (const float*)d_in[9];
    const float* We_a   = (const float*)d_in[10];
    const float* Ws_a   = (const float*)d_in[11];
    const float* bs_a   = (const float*)d_in[12];
    const float* g1_a   = (const float*)d_in[13];
    const float* b1_a   = (const float*)d_in[14];
    const float* W1_a   = (const float*)d_in[15];
    const float* c1_a   = (const float*)d_in[16];
    const float* W2_a   = (const float*)d_in[17];
    const float* c2_a   = (const float*)d_in[18];
    const float* g2_a   = (const float*)d_in[19];
    const float* b2_a   = (const float*)d_in[20];

    static int smem_set = 0;
    if (!smem_set) {
        cudaFuncSetAttribute(gemm_mma, cudaFuncAttributeMaxDynamicSharedMemorySize, NG_SMEM);
        cudaFuncSetAttribute(gemm_mma2, cudaFuncAttributeMaxDynamicSharedMemorySize, NG2_SMEM);
        cudaFuncSetAttribute(gemm_edge, cudaFuncAttributeMaxDynamicSharedMemorySize, EG_SMEM);
        smem_set = 1;
    }

    float *out_, *y_, *x_, *bqkvs_;
    double* red_;
    __half *eh3_, *xeh_, *xc_, *yc_, *hc_, *wt_;
    cudaGetSymbolAddress((void**)&eh3_,  g_e_h3);
    cudaGetSymbolAddress((void**)&out_,  g_out);
    cudaGetSymbolAddress((void**)&y_,    g_y);
    cudaGetSymbolAddress((void**)&x_,    g_x);
    cudaGetSymbolAddress((void**)&red_,  g_red);
    cudaGetSymbolAddress((void**)&bqkvs_, g_bqkvs);
    cudaGetSymbolAddress((void**)&xeh_,  g_xe_h);
    cudaGetSymbolAddress((void**)&xc_,   g_x_cat);
    cudaGetSymbolAddress((void**)&yc_,   g_y_cat);
    cudaGetSymbolAddress((void**)&hc_,   g_h_cat);
    cudaGetSymbolAddress((void**)&wt_,   g_wt_cat);

    const int elem4 = LN_CNT / 4;

    // CSR build (also zeroes the 12 LN accumulators)
    zero_deg<<<(N_NODES + 255) / 256, 256>>>();
    hist_dst<<<(N_EDGES + 255) / 256, 256>>>(ei);
    scan16k<<<1, 1024>>>();
    scatter_perm<<<(N_EDGES + 255) / 256, 256>>>(ei, x_dist);

    // conversions + weight prep
    cvt_cat2<<<(elem4 + 255) / 256, 256>>>(x_in, xc_, DIM, elem4);
    cvt_h_gather<<<(N_EDGES * 64) / 256, 256>>>(x_edge, xeh_);
    pack_bias<<<3, 1024>>>(bq_a, bk_a, bv_a, bs_a);
    dim3 tb(32, 8);
    for (int b = 0; b < 3; b++) {
        size_t wb = (size_t)b * WB;
        __half* wq = wt_ + wb + OW_QKVS;
        tconv<<<dim3(8, 8),  tb>>>(Wq_a + (size_t)b * DIM * DIM, wq,             DIM, DIM, 2);
        tconv<<<dim3(8, 8),  tb>>>(Wk_a + (size_t)b * DIM * DIM, wq + 256 * 512, DIM, DIM, 2);
        tconv<<<dim3(8, 8),  tb>>>(Wv_a + (size_t)b * DIM * DIM, wq + 512 * 512, DIM, DIM, 2);
        tconv<<<dim3(8, 8),  tb>>>(Ws_a + (size_t)b * DIM * DIM, wq + 768 * 512, DIM, DIM, 2);
        tconv<<<dim3(8, 8),  tb>>>(We_a + (size_t)b * DIM * DIM, wt_ + wb + OW_E, DIM, DIM, 1);
        tconv<<<dim3(32, 8), tb>>>(W1_a + (size_t)b * DIM * HID, wt_ + wb + OW_1, DIM, HID, 2);
        tconv<<<dim3(8, 32), tb>>>(W2_a + (size_t)b * HID * DIM, wt_ + wb + OW_2, HID, DIM, 2);
    }

    // edge projections for all blocks, output already CSR-ordered
    gemm_edge<<<N_EDGES / 128, 128, EG_SMEM>>>(xeh_, wt_, eh3_);

    const float* xcur = x_in;
    for (int blk = 0; blk < 3; blk++) {
        size_t wb = (size_t)blk * WB;
        const float* g1 = g1_a + blk * DIM;
        const float* b1 = b1_a + blk * DIM;
        const float* c1 = c1_a + blk * HID;
        const float* c2 = c2_a + blk * DIM;
        const float* g2 = g2_a + blk * DIM;
        const float* b2 = b2_a + blk * DIM;
        double* redb = red_ + blk * 4;

        // QKVS projection: q/skip fp32, k/v fp16 (mode 2 split epilogue)
        gemm_mma<<<dim3(8, 125), 128, NG_SMEM>>>(
            xc_, wt_ + wb + OW_QKVS, bqkvs_ + blk * 1024,
            nullptr, N_NODES, 1024, 512, 0, 2);

        attn_csr<<<N_NODES / 8, 256>>>(eh3_ + (size_t)blk * N_EDGES * DIM,
                                       xcur, y_, redb + 0);
        lnapply<<<elem4 / 256, 256>>>(y_, g1, b1, y_, yc_, redb + 0);

        gemm_mma<<<dim3(8, 125), 128, NG_SMEM>>>(
            yc_, wt_ + wb + OW_1, c1, hc_, N_NODES, HID, 512, 1, 1);
        // FFN2 + residual(y) + LN reduction fused
        gemm_mma2<<<dim3(1, 125), 256, NG2_SMEM>>>(
            hc_, wt_ + wb + OW_2, c2, y_, out_, redb + 2, N_NODES, DIM, 2048);

        float* xdst = (blk == 2) ? (float*)d_out : x_;
        __half* xcat = (blk == 2) ? nullptr : xc_;
        lnapply<<<elem4 / 256, 256>>>(out_, g2, b2, xdst, xcat, redb + 2);

        xcur = x_;
    }
}

// round 16
// speedup vs baseline: 1.7153x; 1.1188x over previous
#include <cuda_runtime.h>
#include <cuda_fp16.h>
#include <math.h>
#include <stdint.h>

#define N_NODES 16000
#define N_EDGES 256000
#define DIM 256
#define HEADS 8
#define HID 1024
#define LN_CNT (N_NODES * DIM)
#define LN_EPS 1e-5f
#define RSQRT_DH 0.17677669529663687f

// weight table offsets (halves, per transformer block); all plain fp16 [N,K]
#define OW_QKVS 0              // [1024, 256]
#define OW_E    262144         // [256, 256]
#define OW_1    327680         // [1024, 256]
#define OW_2    589824         // [256, 1024]
#define WB      851968

// ---------------- scratch -----------------------------------------------------
__device__ float    g_q[(size_t)N_NODES * 256];
__device__ float    g_skip[(size_t)N_NODES * 256];
__device__ __half   g_kv[(size_t)N_NODES * 512];         // [k(256) | v(256)] fp16
__device__ __half   g_e_h3[3 * (size_t)N_EDGES * DIM];   // CSR-ordered
__device__ float    g_out[N_NODES * DIM];
__device__ float    g_y[N_NODES * DIM];
__device__ float    g_x[N_NODES * DIM];
__device__ double   g_red[12];
__device__ float    g_bqkvs[3 * 1024];
__device__ __half   g_xe_h[(size_t)N_EDGES * DIM];       // CSR-ordered gather
__device__ __half   g_x_h[(size_t)N_NODES * DIM];
__device__ __half   g_y_h[(size_t)N_NODES * DIM];
__device__ __half   g_h_h[(size_t)N_NODES * HID];
__device__ __half   g_wt[3 * WB];
// CSR
__device__ int      g_rowstart[N_NODES + 1];
__device__ int      g_cursor[N_NODES];
__device__ int      g_perm[N_EDGES];
__device__ int      g_src_s[N_EDGES];
__device__ float    g_invd_s[N_EDGES];

// ---------------- helpers -----------------------------------------------------
__device__ __forceinline__ uint32_t smem_u32(const void* p) {
    uint32_t a;
    asm("{ .reg .u64 t; cvta.to.shared.u64 t, %1; cvt.u32.u64 %0, t; }"
        : "=r"(a) : "l"(p));
    return a;
}
__device__ __forceinline__ uint32_t pack_h2(__half a, __half b) {
    __half2 h2 = __halves2half2(a, b);
    return *(uint32_t*)&h2;
}
__device__ __forceinline__ void cp16(uint32_t dst, const void* src) {
    asm volatile("cp.async.cg.shared.global [%0], [%1], 16;"
                 :: "r"(dst), "l"(src) : "memory");
}
__device__ __forceinline__ void ldsm_x4(uint32_t* r, uint32_t addr) {
    asm volatile("ldmatrix.sync.aligned.m8n8.x4.shared.b16 {%0,%1,%2,%3}, [%4];"
                 : "=r"(r[0]), "=r"(r[1]), "=r"(r[2]), "=r"(r[3]) : "r"(addr));
}
__device__ __forceinline__ void mma16816(float* c, const uint32_t* a, uint32_t b0, uint32_t b1) {
    asm volatile(
        "mma.sync.aligned.m16n8k16.row.col.f32.f16.f16.f32 "
        "{%0,%1,%2,%3}, {%4,%5,%6,%7}, {%8,%9}, {%0,%1,%2,%3};"
        : "+f"(c[0]), "+f"(c[1]), "+f"(c[2]), "+f"(c[3])
        : "r"(a[0]), "r"(a[1]), "r"(a[2]), "r"(a[3]), "r"(b0), "r"(b1));
}

// qkvs split write: col<256 -> q fp32; [256,512) -> k fp16; [512,768) -> v fp16;
// [768,1024) -> skip fp32
__device__ __forceinline__ void qkvs_emit(int row, int col, float a, float b) {
    if (col < 256) {
        *(float2*)(g_q + (size_t)row * 256 + col) = make_float2(a, b);
    } else if (col < 512) {
        *(__half2*)(g_kv + (size_t)row * 512 + (col - 256)) = __floats2half2_rn(a, b);
    } else if (col < 768) {
        *(__half2*)(g_kv + (size_t)row * 512 + 256 + (col - 512)) = __floats2half2_rn(a, b);
    } else {
        *(float2*)(g_skip + (size_t)row * 256 + (col - 768)) = make_float2(a, b);
    }
}

// ================== node GEMM 128x128 (4 warps, 3-stage) ======================
#define NG_SMEM 98304

__device__ __forceinline__ void load_chunk_n(
    uint32_t st, const __half* __restrict__ A, const __half* __restrict__ B,
    size_t rowA0, size_t rowB0, int K3, int k0, int tid)
{
#pragma unroll
    for (int i = 0; i < 8; i++) {
        int u = tid + (i << 7);
        int row = u >> 3, kk = u & 7;
        uint32_t off = (uint32_t)(row * 128 + kk * 16);
        uint32_t sw = off ^ ((off >> 3) & 0x70);
        cp16(st + sw, A + (rowA0 + row) * (size_t)K3 + k0 + kk * 8);
        cp16(st + 16384 + sw, B + (rowB0 + row) * (size_t)K3 + k0 + kk * 8);
    }
}

__global__ __launch_bounds__(128) void gemm_mma(
    const __half* __restrict__ A, const __half* __restrict__ B,
    const float* __restrict__ bias,
    __half* __restrict__ Ch,
    int M, int N, int K3, int relu, int mode)   // mode 1 = plain fp16 out, 2 = qkvs split
{
    extern __shared__ __align__(128) char smem[];
    uint32_t sbase = smem_u32(smem);

    int tid = threadIdx.x, lane = tid & 31, wid = tid >> 5;
    int warpM = wid >> 1, warpN = wid & 1;
    int tN = blockIdx.x, tM = blockIdx.y;
    size_t rowA0 = (size_t)tM * 128;
    size_t rowB0 = (size_t)tN * 128;
    int nch = K3 >> 6;

    float acc[4][8][4];
#pragma unroll
    for (int i = 0; i < 4; i++)
#pragma unroll
        for (int j = 0; j < 8; j++)
#pragma unroll
            for (int t = 0; t < 4; t++) acc[i][j][t] = 0.f;

    load_chunk_n(sbase, A, B, rowA0, rowB0, K3, 0, tid);
    asm volatile("cp.async.commit_group;" ::: "memory");
    load_chunk_n(sbase + 32768, A, B, rowA0, rowB0, K3, 64, tid);
    asm volatile("cp.async.commit_group;" ::: "memory");

    for (int c = 0; c < nch; c++) {
        if (c + 2 < nch) {
            uint32_t sb = sbase + (uint32_t)((c + 2) % 3) * 32768u;
            load_chunk_n(sb, A, B, rowA0, rowB0, K3, (c + 2) << 6, tid);
            asm volatile("cp.async.commit_group;" ::: "memory");
            asm volatile("cp.async.wait_group 2;" ::: "memory");
        } else if (c + 1 < nch) {
            asm volatile("cp.async.wait_group 1;" ::: "memory");
        } else {
            asm volatile("cp.async.wait_group 0;" ::: "memory");
        }
        __syncthreads();

        uint32_t aB = sbase + (uint32_t)(c % 3) * 32768u;
        uint32_t bB = aB + 16384;
#pragma unroll
        for (int ks = 0; ks < 4; ks++) {
            uint32_t af[4][4], bf[4][4];
#pragma unroll
            for (int mf = 0; mf < 4; mf++) {
                int row = warpM * 64 + mf * 16 + (lane & 15);
                uint32_t off = (uint32_t)(row * 128 + ks * 32 + ((lane >> 4) << 4));
                off ^= (off >> 3) & 0x70;
                ldsm_x4(af[mf], aB + off);
            }
#pragma unroll
            for (int nf2 = 0; nf2 < 4; nf2++) {
                int row = warpN * 64 + nf2 * 16 + (lane & 15);
                uint32_t off = (uint32_t)(row * 128 + ks * 32 + ((lane >> 4) << 4));
                off ^= (off >> 3) & 0x70;
                ldsm_x4(bf[nf2], bB + off);
            }
#pragma unroll
            for (int mf = 0; mf < 4; mf++)
#pragma unroll
                for (int nf2 = 0; nf2 < 4; nf2++) {
                    mma16816(acc[mf][nf2 * 2],     af[mf], bf[nf2][0], bf[nf2][2]);
                    mma16816(acc[mf][nf2 * 2 + 1], af[mf], bf[nf2][1], bf[nf2][3]);
                }
        }
        __syncthreads();
    }

    int m0 = tM * 128 + warpM * 64;
    int n0 = tN * 128 + warpN * 64;
#pragma unroll
    for (int mf = 0; mf < 4; mf++) {
#pragma unroll
        for (int nf = 0; nf < 8; nf++) {
            int r = m0 + mf * 16 + (lane >> 2);
            int col = n0 + nf * 8 + ((lane & 3) << 1);
            float b0 = bias ? __ldg(bias + col) : 0.f;
            float b1 = bias ? __ldg(bias + col + 1) : 0.f;
            float v00 = acc[mf][nf][0] + b0, v01 = acc[mf][nf][1] + b1;
            float v10 = acc[mf][nf][2] + b0, v11 = acc[mf][nf][3] + b1;
            if (relu) {
                v00 = fmaxf(v00, 0.f); v01 = fmaxf(v01, 0.f);
                v10 = fmaxf(v10, 0.f); v11 = fmaxf(v11, 0.f);
            }
            if (mode == 2) {
                qkvs_emit(r, col, v00, v01);
                qkvs_emit(r + 8, col, v10, v11);
            } else {   // mode 1: plain fp16
                *(__half2*)(Ch + (size_t)r * N + col) = __floats2half2_rn(v00, v01);
                *(__half2*)(Ch + (size_t)(r + 8) * N + col) = __floats2half2_rn(v10, v11);
            }
        }
    }
}

// ====== node GEMM 128x256 (8 warps, 2-stage) — FFN2 + residual + LN red ======
#define NG2_SMEM 98304

__device__ __forceinline__ void load_chunk_n2(
    uint32_t st, const __half* __restrict__ A, const __half* __restrict__ B,
    size_t rowA0, size_t rowB0, int K3, int k0, int tid)
{
#pragma unroll
    for (int i = 0; i < 4; i++) {
        int u = tid + (i << 8);
        int row = u >> 3, kk = u & 7;
        uint32_t off = (uint32_t)(row * 128 + kk * 16);
        uint32_t sw = off ^ ((off >> 3) & 0x70);
        cp16(st + sw, A + (rowA0 + row) * (size_t)K3 + k0 + kk * 8);
    }
#pragma unroll
    for (int i = 0; i < 8; i++) {
        int u = tid + (i << 8);
        int row = u >> 3, kk = u & 7;
        uint32_t off = (uint32_t)(row * 128 + kk * 16);
        uint32_t sw = off ^ ((off >> 3) & 0x70);
        cp16(st + 16384 + sw, B + (rowB0 + row) * (size_t)K3 + k0 + kk * 8);
    }
}

__global__ __launch_bounds__(256) void gemm_mma2(
    const __half* __restrict__ A, const __half* __restrict__ B,
    const float* __restrict__ bias, const float* __restrict__ Y,
    float* __restrict__ Cf, double* __restrict__ red,
    int M, int N, int K3)
{
    extern __shared__ __align__(128) char smem[];
    uint32_t sbase = smem_u32(smem);

    int tid = threadIdx.x, lane = tid & 31, wid = tid >> 5;
    int warpM = wid >> 2, warpN = wid & 3;
    int tN = blockIdx.x, tM = blockIdx.y;
    size_t rowA0 = (size_t)tM * 128;
    size_t rowB0 = (size_t)tN * 256;
    int nch = K3 >> 6;

    float acc[4][8][4];
#pragma unroll
    for (int i = 0; i < 4; i++)
#pragma unroll
        for (int j = 0; j < 8; j++)
#pragma unroll
            for (int t = 0; t < 4; t++) acc[i][j][t] = 0.f;

    load_chunk_n2(sbase, A, B, rowA0, rowB0, K3, 0, tid);
    asm volatile("cp.async.commit_group;" ::: "memory");

    for (int c = 0; c < nch; c++) {
        if (c + 1 < nch) {
            uint32_t sb = sbase + (uint32_t)((c + 1) & 1) * 49152u;
            load_chunk_n2(sb, A, B, rowA0, rowB0, K3, (c + 1) << 6, tid);
            asm volatile("cp.async.commit_group;" ::: "memory");
            asm volatile("cp.async.wait_group 1;" ::: "memory");
        } else {
            asm volatile("cp.async.wait_group 0;" ::: "memory");
        }
        __syncthreads();

        uint32_t aB = sbase + (uint32_t)(c & 1) * 49152u;
        uint32_t bB = aB + 16384;
#pragma unroll
        for (int ks = 0; ks < 4; ks++) {
            uint32_t af[4][4], bf[4][4];
#pragma unroll
            for (int mf = 0; mf < 4; mf++) {
                int row = warpM * 64 + mf * 16 + (lane & 15);
                uint32_t off = (uint32_t)(row * 128 + ks * 32 + ((lane >> 4) << 4));
                off ^= (off >> 3) & 0x70;
                ldsm_x4(af[mf], aB + off);
            }
#pragma unroll
            for (int nf2 = 0; nf2 < 4; nf2++) {
                int row = warpN * 64 + nf2 * 16 + (lane & 15);
                uint32_t off = (uint32_t)(row * 128 + ks * 32 + ((lane >> 4) << 4));
                off ^= (off >> 3) & 0x70;
                ldsm_x4(bf[nf2], bB + off);
            }
#pragma unroll
            for (int mf = 0; mf < 4; mf++)
#pragma unroll
                for (int nf2 = 0; nf2 < 4; nf2++) {
                    mma16816(acc[mf][nf2 * 2],     af[mf], bf[nf2][0], bf[nf2][2]);
                    mma16816(acc[mf][nf2 * 2 + 1], af[mf], bf[nf2][1], bf[nf2][3]);
                }
        }
        __syncthreads();
    }

    // epilogue: s = acc + bias + y; write; accumulate DP sum/sumsq
    int m0 = tM * 128 + warpM * 64;
    int n0 = tN * 256 + warpN * 64;
    double ls = 0.0, lq = 0.0;
#pragma unroll
    for (int mf = 0; mf < 4; mf++) {
#pragma unroll
        for (int nf = 0; nf < 8; nf++) {
            int r = m0 + mf * 16 + (lane >> 2);
            int col = n0 + nf * 8 + ((lane & 3) << 1);
            float b0 = bias ? __ldg(bias + col) : 0.f;
            float b1 = bias ? __ldg(bias + col + 1) : 0.f;
            float2 y0 = *(const float2*)(Y + (size_t)r * N + col);
            float2 y1 = *(const float2*)(Y + (size_t)(r + 8) * N + col);
            float s00 = acc[mf][nf][0] + b0 + y0.x;
            float s01 = acc[mf][nf][1] + b1 + y0.y;
            float s10 = acc[mf][nf][2] + b0 + y1.x;
            float s11 = acc[mf][nf][3] + b1 + y1.y;
            *(float2*)(Cf + (size_t)r * N + col) = make_float2(s00, s01);
            *(float2*)(Cf + (size_t)(r + 8) * N + col) = make_float2(s10, s11);
            ls += (double)s00 + (double)s01 + (double)s10 + (double)s11;
            lq += (double)s00 * s00 + (double)s01 * s01 +
                  (double)s10 * s10 + (double)s11 * s11;
        }
    }
#pragma unroll
    for (int o = 16; o > 0; o >>= 1) {
        ls += __shfl_down_sync(0xffffffffu, ls, o);
        lq += __shfl_down_sync(0xffffffffu, lq, o);
    }
    __shared__ double shs[8], shq[8];
    if (lane == 0) { shs[wid] = ls; shq[wid] = lq; }
    __syncthreads();
    if (tid == 0) {
        double ts = 0, tq = 0;
#pragma unroll
        for (int k = 0; k < 8; k++) { ts += shs[k]; tq += shq[k]; }
        atomicAdd(&red[0], ts);
        atomicAdd(&red[1], tq);
    }
}

// ================== edge GEMM: A-resident, all 3 blocks (1-cat) ===============
#define EG_SMEM 98304

__global__ __launch_bounds__(128) void gemm_edge(
    const __half* __restrict__ XE, const __half* __restrict__ WT,
    __half* __restrict__ EH)
{
    extern __shared__ __align__(128) char smem[];
    uint32_t sbase = smem_u32(smem);
    uint32_t bbase = sbase + 65536;

    int tid = threadIdx.x, lane = tid & 31, wid = tid >> 5;
    int warpM = wid >> 1, warpN = wid & 1;
    size_t rowA0 = (size_t)blockIdx.x * 128;

#pragma unroll
    for (int ch = 0; ch < 4; ch++) {
#pragma unroll
        for (int i = 0; i < 8; i++) {
            int u = tid + (i << 7);
            int row = u >> 3, kk = u & 7;
            uint32_t off = (uint32_t)(row * 128 + kk * 16);
            uint32_t sw = off ^ ((off >> 3) & 0x70);
            cp16(sbase + ch * 16384 + sw, XE + (rowA0 + row) * 256 + ch * 64 + kk * 8);
        }
    }
    {
#pragma unroll
        for (int i = 0; i < 8; i++) {
            int u = tid + (i << 7);
            int row = u >> 3, kk = u & 7;
            uint32_t off = (uint32_t)(row * 128 + kk * 16);
            uint32_t sw = off ^ ((off >> 3) & 0x70);
            cp16(bbase + sw, WT + OW_E + (size_t)row * 256 + kk * 8);
        }
    }
    asm volatile("cp.async.commit_group;" ::: "memory");

    float acc[4][8][4];
#pragma unroll
    for (int i = 0; i < 4; i++)
#pragma unroll
        for (int j = 0; j < 8; j++)
#pragma unroll
            for (int t = 0; t < 4; t++) acc[i][j][t] = 0.f;

    for (int it = 0; it < 24; it++) {
        if (it < 23) {
            int j = it + 1;
            int wt = j >> 2, ck = j & 3;
            int blkj = wt >> 1, nh = wt & 1;
            const __half* Bp = WT + (size_t)blkj * WB + OW_E;
            uint32_t bb = bbase + (uint32_t)(j & 1) * 16384u;
#pragma unroll
            for (int i = 0; i < 8; i++) {
                int u = tid + (i << 7);
                int row = u >> 3, kk = u & 7;
                uint32_t off = (uint32_t)(row * 128 + kk * 16);
                uint32_t sw = off ^ ((off >> 3) & 0x70);
                cp16(bb + sw, Bp + (size_t)(nh * 128 + row) * 256 + ck * 64 + kk * 8);
            }
            asm volatile("cp.async.commit_group;" ::: "memory");
            asm volatile("cp.async.wait_group 1;" ::: "memory");
        } else {
            asm volatile("cp.async.wait_group 0;" ::: "memory");
        }
        __syncthreads();

        int ck = it & 3;
        uint32_t aB = sbase + (uint32_t)ck * 16384u;
        uint32_t bB = bbase + (uint32_t)(it & 1) * 16384u;
#pragma unroll
        for (int ks = 0; ks < 4; ks++) {
            uint32_t af[4][4], bf[4][4];
#pragma unroll
            for (int mf = 0; mf < 4; mf++) {
                int row = warpM * 64 + mf * 16 + (lane & 15);
                uint32_t off = (uint32_t)(row * 128 + ks * 32 + ((lane >> 4) << 4));
                off ^= (off >> 3) & 0x70;
                ldsm_x4(af[mf], aB + off);
            }
#pragma unroll
            for (int nf2 = 0; nf2 < 4; nf2++) {
                int row = warpN * 64 + nf2 * 16 + (lane & 15);
                uint32_t off = (uint32_t)(row * 128 + ks * 32 + ((lane >> 4) << 4));
                off ^= (off >> 3) & 0x70;
                ldsm_x4(bf[nf2], bB + off);
            }
#pragma unroll
            for (int mf = 0; mf < 4; mf++)
#pragma unroll
                for (int nf2 = 0; nf2 < 4; nf2++) {
                    mma16816(acc[mf][nf2 * 2],     af[mf], bf[nf2][0], bf[nf2][2]);
                    mma16816(acc[mf][nf2 * 2 + 1], af[mf], bf[nf2][1], bf[nf2][3]);
                }
        }
        __syncthreads();

        if (ck == 3) {
            int wt = it >> 2;
            int blk = wt >> 1, nh = wt & 1;
            __half* out = EH + (size_t)blk * N_EDGES * DIM;
#pragma unroll
            for (int mf = 0; mf < 4; mf++) {
#pragma unroll
                for (int nf = 0; nf < 8; nf++) {
                    int r = (int)rowA0 + warpM * 64 + mf * 16 + (lane >> 2);
                    int col = nh * 128 + warpN * 64 + nf * 8 + ((lane & 3) << 1);
                    *(__half2*)(out + (size_t)r * DIM + col) =
                        __floats2half2_rn(acc[mf][nf][0], acc[mf][nf][1]);
                    *(__half2*)(out + (size_t)(r + 8) * DIM + col) =
                        __floats2half2_rn(acc[mf][nf][2], acc[mf][nf][3]);
#pragma unroll
                    for (int t = 0; t < 4; t++) acc[mf][nf][t] = 0.f;
                }
            }
        }
    }
}

// ---------------- CSR build ----------------------------------------------------
__global__ void zero_deg() {
    int i = blockIdx.x * blockDim.x + threadIdx.x;
    if (i < N_NODES) g_cursor[i] = 0;
    if (i < 12) g_red[i] = 0.0;
}
__global__ void hist_dst(const int* __restrict__ ei) {
    int i = blockIdx.x * blockDim.x + threadIdx.x;
    if (i < N_EDGES) atomicAdd(&g_cursor[ei[N_EDGES + i]], 1);
}
__global__ __launch_bounds__(1024) void scan16k() {
    __shared__ int warp_tot[32];
    int tid = threadIdx.x, lane = tid & 31, wid = tid >> 5;
    int base = tid * 16;
    int vals[16];
    int s = 0;
#pragma unroll
    for (int t = 0; t < 16; t++) {
        int idx = base + t;
        int v = (idx < N_NODES) ? g_cursor[idx] : 0;
        vals[t] = s;
        s += v;
    }
    int x = s;
#pragma unroll
    for (int o = 1; o < 32; o <<= 1) {
        int n = __shfl_up_sync(0xffffffffu, x, o);
        if (lane >= o) x += n;
    }
    if (lane == 31) warp_tot[wid] = x;
    __syncthreads();
    if (wid == 0) {
        int t = warp_tot[lane];
        int y = t;
#pragma unroll
        for (int o = 1; o < 32; o <<= 1) {
            int n = __shfl_up_sync(0xffffffffu, y, o);
            if (lane >= o) y += n;
        }
        warp_tot[lane] = y - t;
    }
    __syncthreads();
    int offset = warp_tot[wid] + (x - s);
#pragma unroll
    for (int t = 0; t < 16; t++) {
        int idx = base + t;
        if (idx < N_NODES) g_rowstart[idx] = offset + vals[t];
    }
    if (tid == 1023) g_rowstart[N_NODES] = offset + s;
    __syncthreads();
#pragma unroll
    for (int t = 0; t < 16; t++) {
        int idx = base + t;
        if (idx < N_NODES) g_cursor[idx] = g_rowstart[idx];
    }
}
__global__ void scatter_perm(const int* __restrict__ ei,
                             const float* __restrict__ xdist) {
    int i = blockIdx.x * blockDim.x + threadIdx.x;
    if (i < N_EDGES) {
        int d = ei[N_EDGES + i];
        int pos = atomicAdd(&g_cursor[d], 1);
        g_perm[pos] = i;
        g_src_s[pos] = ei[i];
        g_invd_s[pos] = 1.0f / xdist[i];
    }
}

// ---------------- converters / weight prep -------------------------------------
__global__ __launch_bounds__(256) void cvt_h(
    const float* __restrict__ s, __half* __restrict__ d, int n4)
{
    int i = blockIdx.x * blockDim.x + threadIdx.x;
    if (i >= n4) return;
    float4 v = ((const float4*)s)[i];
    *(uint2*)(d + (size_t)i * 4) =
        make_uint2(pack_h2(__float2half_rn(v.x), __float2half_rn(v.y)),
                   pack_h2(__float2half_rn(v.z), __float2half_rn(v.w)));
}

// gathered fp32->fp16: row i of dst = row perm[i] of src (256 cols)
__global__ __launch_bounds__(256) void cvt_h_gather(
    const float* __restrict__ s, __half* __restrict__ d)
{
    int tid = blockIdx.x * blockDim.x + threadIdx.x;
    int row = tid >> 6;
    int col = (tid & 63) * 4;
    if (row >= N_EDGES) return;
    int srow = g_perm[row];
    float4 v = *(const float4*)(s + (size_t)srow * DIM + col);
    *(uint2*)(d + (size_t)row * DIM + col) =
        make_uint2(pack_h2(__float2half_rn(v.x), __float2half_rn(v.y)),
                   pack_h2(__float2half_rn(v.z), __float2half_rn(v.w)));
}

// W [K,N] row-major -> out [N, K] fp16 (transpose)
__global__ void tconv(const float* __restrict__ W, __half* __restrict__ out,
                      int K, int N)
{
    __shared__ float t[32][33];
    int tx = threadIdx.x, ty = threadIdx.y;
    int n0 = blockIdx.x * 32, k0 = blockIdx.y * 32;
#pragma unroll
    for (int r = 0; r < 4; r++)
        t[ty + 8 * r][tx] = W[(size_t)(k0 + ty + 8 * r) * N + n0 + tx];
    __syncthreads();
#pragma unroll
    for (int r = 0; r < 4; r++) {
        int nl = ty + 8 * r;
        out[(size_t)(n0 + nl) * K + k0 + tx] = __float2half_rn(t[tx][nl]);
    }
}

__global__ void pack_bias(const float* __restrict__ bq, const float* __restrict__ bk,
                          const float* __restrict__ bv, const float* __restrict__ bs)
{
    int b = blockIdx.x, t = threadIdx.x;
    float v = (t < 256) ? bq[b * 256 + t]
            : (t < 512) ? bk[b * 256 + t - 256]
            : (t < 768) ? bv[b * 256 + t - 512]
                        : bs[b * 256 + t - 768];
    g_bqkvs[b * 1024 + t] = v;
}

// ---------------- fused CSR attention + skip + residual + LN reduction ---------
__global__ __launch_bounds__(256) void attn_csr(
    const __half* __restrict__ eh, const float* __restrict__ x,
    float* __restrict__ y, double* __restrict__ red)
{
    int tid = threadIdx.x, lane = tid & 31, wid = tid >> 5;
    int node = blockIdx.x * 8 + wid;

    double ls = 0.0, lq = 0.0;
    if (node < N_NODES) {
        const float* qrow = g_q + (size_t)node * 256;
        float4 q0 = *(const float4*)(qrow + lane * 8);
        float4 q1 = *(const float4*)(qrow + lane * 8 + 4);

        int start = g_rowstart[node];
        int end   = g_rowstart[node + 1];

        float m0 = 0.f, m1 = 0.f, m2 = 0.f, m3 = 0.f;
        float m4 = 0.f, m5 = 0.f, m6 = 0.f, m7 = 0.f;
        float denom = 0.f;

        for (int j = start; j < end; j++) {
            int src = g_src_s[j];
            float invd = g_invd_s[j];

            const __half* kvrow = g_kv + (size_t)src * 512;
            int4 kvi = *(const int4*)(kvrow + lane * 8);
            int4 vvi = *(const int4*)(kvrow + 256 + lane * 8);
            int4 evi = *(const int4*)(eh + (size_t)j * DIM + lane * 8);
            __half2* kp = (__half2*)&kvi;
            __half2* vp = (__half2*)&vvi;
            __half2* ep = (__half2*)&evi;
            float2 k0 = __half22float2(kp[0]), k1 = __half22float2(kp[1]);
            float2 k2 = __half22float2(kp[2]), k3 = __half22float2(kp[3]);
            float2 e0 = __half22float2(ep[0]), e1 = __half22float2(ep[1]);
            float2 e2 = __half22float2(ep[2]), e3 = __half22float2(ep[3]);

            float p = 0.f;
            p = fmaf(q0.x, k0.x + e0.x, p);
            p = fmaf(q0.y, k0.y + e0.y, p);
            p = fmaf(q0.z, k1.x + e1.x, p);
            p = fmaf(q0.w, k1.y + e1.y, p);
            p = fmaf(q1.x, k2.x + e2.x, p);
            p = fmaf(q1.y, k2.y + e2.y, p);
            p = fmaf(q1.z, k3.x + e3.x, p);
            p = fmaf(q1.w, k3.y + e3.y, p);
            p += __shfl_xor_sync(0xffffffffu, p, 1);
            p += __shfl_xor_sync(0xffffffffu, p, 2);

            float ex = __expf(p * invd * RSQRT_DH);
            denom += ex;

            float2 v0 = __half22float2(vp[0]), v1 = __half22float2(vp[1]);
            float2 v2 = __half22float2(vp[2]), v3 = __half22float2(vp[3]);
            m0 = fmaf(v0.x + e0.x, ex, m0);
            m1 = fmaf(v0.y + e0.y, ex, m1);
            m2 = fmaf(v1.x + e1.x, ex, m2);
            m3 = fmaf(v1.y + e1.y, ex, m3);
            m4 = fmaf(v2.x + e2.x, ex, m4);
            m5 = fmaf(v2.y + e2.y, ex, m5);
            m6 = fmaf(v3.x + e3.x, ex, m6);
            m7 = fmaf(v3.y + e3.y, ex, m7);
        }

        float inv = 1.0f / (denom + 1e-16f);
        const float* xr = x + (size_t)node * 256 + lane * 8;
        const float* sk = g_skip + (size_t)node * 256 + lane * 8;
        float4 xv0 = *(const float4*)(xr);
        float4 xv1 = *(const float4*)(xr + 4);
        float4 sk0 = *(const float4*)(sk);
        float4 sk1 = *(const float4*)(sk + 4);

        float r0 = xv0.x + sk0.x + m0 * inv;
        float r1 = xv0.y + sk0.y + m1 * inv;
        float r2 = xv0.z + sk0.z + m2 * inv;
        float r3 = xv0.w + sk0.w + m3 * inv;
        float r4 = xv1.x + sk1.x + m4 * inv;
        float r5 = xv1.y + sk1.y + m5 * inv;
        float r6 = xv1.z + sk1.z + m6 * inv;
        float r7 = xv1.w + sk1.w + m7 * inv;

        float* yp = y + (size_t)node * 256 + lane * 8;
        *(float4*)(yp)     = make_float4(r0, r1, r2, r3);
        *(float4*)(yp + 4) = make_float4(r4, r5, r6, r7);

        ls = (double)r0 + (double)r1 + (double)r2 + (double)r3 +
             (double)r4 + (double)r5 + (double)r6 + (double)r7;
        lq = (double)r0 * r0 + (double)r1 * r1 + (double)r2 * r2 + (double)r3 * r3 +
             (double)r4 * r4 + (double)r5 * r5 + (double)r6 * r6 + (double)r7 * r7;
    }

#pragma unroll
    for (int o = 16; o > 0; o >>= 1) {
        ls += __shfl_down_sync(0xffffffffu, ls, o);
        lq += __shfl_down_sync(0xffffffffu, lq, o);
    }
    __shared__ double shs[8], shq[8];
    if (lane == 0) { shs[wid] = ls; shq[wid] = lq; }
    __syncthreads();
    if (tid == 0) {
        double ts = 0, tq = 0;
#pragma unroll
        for (int k = 0; k < 8; k++) { ts += shs[k]; tq += shq[k]; }
        atomicAdd(&red[0], ts);
        atomicAdd(&red[1], tq);
    }
}

// ---------------- graph layernorm apply + optional plain fp16 emit -------------
__global__ __launch_bounds__(256) void lnapply(
    const float* __restrict__ y, const float* __restrict__ g,
    const float* __restrict__ b, float* __restrict__ o,
    __half* __restrict__ oh, const double* __restrict__ red)
{
    int i = blockIdx.x * blockDim.x + threadIdx.x;
    double mean = red[0] / (double)LN_CNT;
    double var  = red[1] / (double)LN_CNT - mean * mean;
    if (var < 0) var = 0;
    float inv = 1.0f / ((float)sqrt(var) + LN_EPS);
    float mu = (float)mean;

    int i4 = i * 4;
    int c = i4 % DIM;
    float4 yv = ((const float4*)y)[i];
    float4 gv = *(const float4*)(g + c);
    float4 bv = *(const float4*)(b + c);
    float4 r;
    r.x = (yv.x - mu) * inv * gv.x + bv.x;
    r.y = (yv.y - mu) * inv * gv.y + bv.y;
    r.z = (yv.z - mu) * inv * gv.z + bv.z;
    r.w = (yv.w - mu) * inv * gv.w + bv.w;
    ((float4*)o)[i] = r;

    if (oh) {
        *(uint2*)(oh + (size_t)i4) =
            make_uint2(pack_h2(__float2half_rn(r.x), __float2half_rn(r.y)),
                       pack_h2(__float2half_rn(r.z), __float2half_rn(r.w)));
    }
}

// ---------------- host orchestration -------------------------------------------
extern "C" void kernel_launch(void* const* d_in, const int* in_sizes, int n_in,
                              void* d_out, int out_size)
{
    const float* x_in   = (const float*)d_in[0];
    const int*   ei     = (const int*)d_in[1];
    const float* x_edge = (const float*)d_in[2];
    const float* x_dist = (const float*)d_in[3];
    const float* Wq_a   = (const float*)d_in[4];
    const float* bq_a   = (const float*)d_in[5];
    const float* Wk_a   = (const float*)d_in[6];
    const float* bk_a   = (const float*)d_in[7];
    const float* Wv_a   = (const float*)d_in[8];
    const float* bv_a   = (const float*)d_in[9];
    const float* We_a   = (const float*)d_in[10];
    const float* Ws_a   = (const float*)d_in[11];
    const float* bs_a   = (const float*)d_in[12];
    const float* g1_a   = (const float*)d_in[13];
    const float* b1_a   = (const float*)d_in[14];
    const float* W1_a   = (const float*)d_in[15];
    const float* c1_a   = (const float*)d_in[16];
    const float* W2_a   = (const float*)d_in[17];
    const float* c2_a   = (const float*)d_in[18];
    const float* g2_a   = (const float*)d_in[19];
    const float* b2_a   = (const float*)d_in[20];

    static int smem_set = 0;
    if (!smem_set) {
        cudaFuncSetAttribute(gemm_mma, cudaFuncAttributeMaxDynamicSharedMemorySize, NG_SMEM);
        cudaFuncSetAttribute(gemm_mma2, cudaFuncAttributeMaxDynamicSharedMemorySize, NG2_SMEM);
        cudaFuncSetAttribute(gemm_edge, cudaFuncAttributeMaxDynamicSharedMemorySize, EG_SMEM);
        smem_set = 1;
    }

    float *out_, *y_, *x_, *bqkvs_;
    double* red_;
    __half *eh3_, *xeh_, *xh_, *yh_, *hh_, *wt_;
    cudaGetSymbolAddress((void**)&eh3_,  g_e_h3);
    cudaGetSymbolAddress((void**)&out_,  g_out);
    cudaGetSymbolAddress((void**)&y_,    g_y);
    cudaGetSymbolAddress((void**)&x_,    g_x);
    cudaGetSymbolAddress((void**)&red_,  g_red);
    cudaGetSymbolAddress((void**)&bqkvs_, g_bqkvs);
    cudaGetSymbolAddress((void**)&xeh_,  g_xe_h);
    cudaGetSymbolAddress((void**)&xh_,   g_x_h);
    cudaGetSymbolAddress((void**)&yh_,   g_y_h);
    cudaGetSymbolAddress((void**)&hh_,   g_h_h);
    cudaGetSymbolAddress((void**)&wt_,   g_wt);

    const int elem4 = LN_CNT / 4;

    // CSR build (also zeroes the 12 LN accumulators)
    zero_deg<<<(N_NODES + 255) / 256, 256>>>();
    hist_dst<<<(N_EDGES + 255) / 256, 256>>>(ei);
    scan16k<<<1, 1024>>>();
    scatter_perm<<<(N_EDGES + 255) / 256, 256>>>(ei, x_dist);

    // conversions + weight prep
    cvt_h<<<(elem4 + 255) / 256, 256>>>(x_in, xh_, elem4);
    cvt_h_gather<<<(N_EDGES * 64) / 256, 256>>>(x_edge, xeh_);
    pack_bias<<<3, 1024>>>(bq_a, bk_a, bv_a, bs_a);
    dim3 tb(32, 8);
    for (int b = 0; b < 3; b++) {
        size_t wb = (size_t)b * WB;
        __half* wq = wt_ + wb + OW_QKVS;
        tconv<<<dim3(8, 8),  tb>>>(Wq_a + (size_t)b * DIM * DIM, wq,             DIM, DIM);
        tconv<<<dim3(8, 8),  tb>>>(Wk_a + (size_t)b * DIM * DIM, wq + 256 * 256, DIM, DIM);
        tconv<<<dim3(8, 8),  tb>>>(Wv_a + (size_t)b * DIM * DIM, wq + 512 * 256, DIM, DIM);
        tconv<<<dim3(8, 8),  tb>>>(Ws_a + (size_t)b * DIM * DIM, wq + 768 * 256, DIM, DIM);
        tconv<<<dim3(8, 8),  tb>>>(We_a + (size_t)b * DIM * DIM, wt_ + wb + OW_E, DIM, DIM);
        tconv<<<dim3(32, 8), tb>>>(W1_a + (size_t)b * DIM * HID, wt_ + wb + OW_1, DIM, HID);
        tconv<<<dim3(8, 32), tb>>>(W2_a + (size_t)b * HID * DIM, wt_ + wb + OW_2, HID, DIM);
    }

    // edge projections for all blocks, output already CSR-ordered
    gemm_edge<<<N_EDGES / 128, 128, EG_SMEM>>>(xeh_, wt_, eh3_);

    const float* xcur = x_in;
    const __half* xhcur = xh_;
    for (int blk = 0; blk < 3; blk++) {
        size_t wb = (size_t)blk * WB;
        const float* g1 = g1_a + blk * DIM;
        const float* b1 = b1_a + blk * DIM;
        const float* c1 = c1_a + blk * HID;
        const float* c2 = c2_a + blk * DIM;
        const float* g2 = g2_a + blk * DIM;
        const float* b2 = b2_a + blk * DIM;
        double* redb = red_ + blk * 4;

        // QKVS projection: q/skip fp32, k/v fp16 (mode 2 split epilogue)
        gemm_mma<<<dim3(8, 125), 128, NG_SMEM>>>(
            xhcur, wt_ + wb + OW_QKVS, bqkvs_ + blk * 1024,
            nullptr, N_NODES, 1024, 256, 0, 2);

        attn_csr<<<N_NODES / 8, 256>>>(eh3_ + (size_t)blk * N_EDGES * DIM,
                                       xcur, y_, redb + 0);
        lnapply<<<elem4 / 256, 256>>>(y_, g1, b1, y_, yh_, redb + 0);

        gemm_mma<<<dim3(8, 125), 128, NG_SMEM>>>(
            yh_, wt_ + wb + OW_1, c1, hh_, N_NODES, HID, 256, 1, 1);
        // FFN2 + residual(y) + LN reduction fused
        gemm_mma2<<<dim3(1, 125), 256, NG2_SMEM>>>(
            hh_, wt_ + wb + OW_2, c2, y_, out_, redb + 2, N_NODES, DIM, 1024);

        float* xdst = (blk == 2) ? (float*)d_out : x_;
        __half* xhdst = (blk == 2) ? nullptr : xh_;
        lnapply<<<elem4 / 256, 256>>>(out_, g2, b2, xdst, xhdst, redb + 2);

        xcur = x_;
        xhcur = xh_;
    }
}

// round 17
// speedup vs baseline: 1.7652x; 1.0291x over previous
#include <cuda_runtime.h>
#include <cuda_fp16.h>
#include <math.h>
#include <stdint.h>

#define N_NODES 16000
#define N_EDGES 256000
#define DIM 256
#define HEADS 8
#define HID 1024
#define LN_CNT (N_NODES * DIM)
#define LN_EPS 1e-5f
#define RSQRT_DH 0.17677669529663687f

// weight table offsets (halves, per transformer block); all plain fp16 [N,K]
#define OW_QKVS 0              // [1024, 256]
#define OW_E    262144         // [256, 256]
#define OW_1    327680         // [1024, 256]
#define OW_2    589824         // [256, 1024]
#define WB      851968

// ---------------- scratch -----------------------------------------------------
__device__ float    g_q[(size_t)N_NODES * 256];
__device__ float    g_skip[(size_t)N_NODES * 256];
__device__ __half   g_kv[(size_t)N_NODES * 512];         // [k(256) | v(256)] fp16
__device__ __half   g_e_h3[3 * (size_t)N_EDGES * DIM];   // CSR-ordered
__device__ float    g_out[N_NODES * DIM];
__device__ float    g_y[N_NODES * DIM];
__device__ float    g_x[N_NODES * DIM];
__device__ double   g_red[12];
__device__ float    g_bqkvs[3 * 1024];
__device__ __half   g_xe_h[(size_t)N_EDGES * DIM];       // CSR-ordered gather
__device__ __half   g_x_h[(size_t)N_NODES * DIM];
__device__ __half   g_y_h[(size_t)N_NODES * DIM];
__device__ __half   g_h_h[(size_t)N_NODES * HID];
__device__ __half   g_wt[3 * WB];
// CSR
__device__ int      g_rowstart[N_NODES + 1];
__device__ int      g_cursor[N_NODES];
__device__ int      g_perm[N_EDGES];
__device__ int      g_src_s[N_EDGES];
__device__ float    g_invd_s[N_EDGES];

// ---------------- helpers -----------------------------------------------------
__device__ __forceinline__ uint32_t smem_u32(const void* p) {
    uint32_t a;
    asm("{ .reg .u64 t; cvta.to.shared.u64 t, %1; cvt.u32.u64 %0, t; }"
        : "=r"(a) : "l"(p));
    return a;
}
__device__ __forceinline__ uint32_t pack_h2(__half a, __half b) {
    __half2 h2 = __halves2half2(a, b);
    return *(uint32_t*)&h2;
}
__device__ __forceinline__ void cp16(uint32_t dst, const void* src) {
    asm volatile("cp.async.cg.shared.global [%0], [%1], 16;"
                 :: "r"(dst), "l"(src) : "memory");
}
__device__ __forceinline__ void ldsm_x4(uint32_t* r, uint32_t addr) {
    asm volatile("ldmatrix.sync.aligned.m8n8.x4.shared.b16 {%0,%1,%2,%3}, [%4];"
                 : "=r"(r[0]), "=r"(r[1]), "=r"(r[2]), "=r"(r[3]) : "r"(addr));
}
__device__ __forceinline__ void mma16816(float* c, const uint32_t* a, uint32_t b0, uint32_t b1) {
    asm volatile(
        "mma.sync.aligned.m16n8k16.row.col.f32.f16.f16.f32 "
        "{%0,%1,%2,%3}, {%4,%5,%6,%7}, {%8,%9}, {%0,%1,%2,%3};"
        : "+f"(c[0]), "+f"(c[1]), "+f"(c[2]), "+f"(c[3])
        : "r"(a[0]), "r"(a[1]), "r"(a[2]), "r"(a[3]), "r"(b0), "r"(b1));
}

// qkvs split write
__device__ __forceinline__ void qkvs_emit(int row, int col, float a, float b) {
    if (col < 256) {
        *(float2*)(g_q + (size_t)row * 256 + col) = make_float2(a, b);
    } else if (col < 512) {
        *(__half2*)(g_kv + (size_t)row * 512 + (col - 256)) = __floats2half2_rn(a, b);
    } else if (col < 768) {
        *(__half2*)(g_kv + (size_t)row * 512 + 256 + (col - 512)) = __floats2half2_rn(a, b);
    } else {
        *(float2*)(g_skip + (size_t)row * 256 + (col - 768)) = make_float2(a, b);
    }
}

// ================== node GEMM 128x128 (4 warps, 3-stage) ======================
#define NG_SMEM 98304

__device__ __forceinline__ void load_chunk_n(
    uint32_t st, const __half* __restrict__ A, const __half* __restrict__ B,
    size_t rowA0, size_t rowB0, int K3, int k0, int tid)
{
#pragma unroll
    for (int i = 0; i < 8; i++) {
        int u = tid + (i << 7);
        int row = u >> 3, kk = u & 7;
        uint32_t off = (uint32_t)(row * 128 + kk * 16);
        uint32_t sw = off ^ ((off >> 3) & 0x70);
        cp16(st + sw, A + (rowA0 + row) * (size_t)K3 + k0 + kk * 8);
        cp16(st + 16384 + sw, B + (rowB0 + row) * (size_t)K3 + k0 + kk * 8);
    }
}

__global__ __launch_bounds__(128) void gemm_mma(
    const __half* __restrict__ A, const __half* __restrict__ B,
    const float* __restrict__ bias,
    __half* __restrict__ Ch,
    int M, int N, int K3, int relu, int mode)   // mode 1 = plain fp16 out, 2 = qkvs split
{
    extern __shared__ __align__(128) char smem[];
    uint32_t sbase = smem_u32(smem);

    int tid = threadIdx.x, lane = tid & 31, wid = tid >> 5;
    int warpM = wid >> 1, warpN = wid & 1;
    int tN = blockIdx.x, tM = blockIdx.y;
    size_t rowA0 = (size_t)tM * 128;
    size_t rowB0 = (size_t)tN * 128;
    int nch = K3 >> 6;

    float acc[4][8][4];
#pragma unroll
    for (int i = 0; i < 4; i++)
#pragma unroll
        for (int j = 0; j < 8; j++)
#pragma unroll
            for (int t = 0; t < 4; t++) acc[i][j][t] = 0.f;

    load_chunk_n(sbase, A, B, rowA0, rowB0, K3, 0, tid);
    asm volatile("cp.async.commit_group;" ::: "memory");
    if (nch > 1) {
        load_chunk_n(sbase + 32768, A, B, rowA0, rowB0, K3, 64, tid);
    }
    asm volatile("cp.async.commit_group;" ::: "memory");

    for (int c = 0; c < nch; c++) {
        if (c + 2 < nch) {
            uint32_t sb = sbase + (uint32_t)((c + 2) % 3) * 32768u;
            load_chunk_n(sb, A, B, rowA0, rowB0, K3, (c + 2) << 6, tid);
            asm volatile("cp.async.commit_group;" ::: "memory");
            asm volatile("cp.async.wait_group 2;" ::: "memory");
        } else if (c + 1 < nch) {
            asm volatile("cp.async.wait_group 1;" ::: "memory");
        } else {
            asm volatile("cp.async.wait_group 0;" ::: "memory");
        }
        __syncthreads();

        uint32_t aB = sbase + (uint32_t)(c % 3) * 32768u;
        uint32_t bB = aB + 16384;
#pragma unroll
        for (int ks = 0; ks < 4; ks++) {
            uint32_t af[4][4], bf[4][4];
#pragma unroll
            for (int mf = 0; mf < 4; mf++) {
                int row = warpM * 64 + mf * 16 + (lane & 15);
                uint32_t off = (uint32_t)(row * 128 + ks * 32 + ((lane >> 4) << 4));
                off ^= (off >> 3) & 0x70;
                ldsm_x4(af[mf], aB + off);
            }
#pragma unroll
            for (int nf2 = 0; nf2 < 4; nf2++) {
                int row = warpN * 64 + nf2 * 16 + (lane & 15);
                uint32_t off = (uint32_t)(row * 128 + ks * 32 + ((lane >> 4) << 4));
                off ^= (off >> 3) & 0x70;
                ldsm_x4(bf[nf2], bB + off);
            }
#pragma unroll
            for (int mf = 0; mf < 4; mf++)
#pragma unroll
                for (int nf2 = 0; nf2 < 4; nf2++) {
                    mma16816(acc[mf][nf2 * 2],     af[mf], bf[nf2][0], bf[nf2][2]);
                    mma16816(acc[mf][nf2 * 2 + 1], af[mf], bf[nf2][1], bf[nf2][3]);
                }
        }
        __syncthreads();
    }

    int m0 = tM * 128 + warpM * 64;
    int n0 = tN * 128 + warpN * 64;
#pragma unroll
    for (int mf = 0; mf < 4; mf++) {
#pragma unroll
        for (int nf = 0; nf < 8; nf++) {
            int r = m0 + mf * 16 + (lane >> 2);
            int col = n0 + nf * 8 + ((lane & 3) << 1);
            float b0 = bias ? __ldg(bias + col) : 0.f;
            float b1 = bias ? __ldg(bias + col + 1) : 0.f;
            float v00 = acc[mf][nf][0] + b0, v01 = acc[mf][nf][1] + b1;
            float v10 = acc[mf][nf][2] + b0, v11 = acc[mf][nf][3] + b1;
            if (relu) {
                v00 = fmaxf(v00, 0.f); v01 = fmaxf(v01, 0.f);
                v10 = fmaxf(v10, 0.f); v11 = fmaxf(v11, 0.f);
            }
            if (mode == 2) {
                qkvs_emit(r, col, v00, v01);
                qkvs_emit(r + 8, col, v10, v11);
            } else {
                *(__half2*)(Ch + (size_t)r * N + col) = __floats2half2_rn(v00, v01);
                *(__half2*)(Ch + (size_t)(r + 8) * N + col) = __floats2half2_rn(v10, v11);
            }
        }
    }
}

// ====== node GEMM 128x256 (8 warps, 2-stage) — FFN2 + residual + LN red ======
#define NG2_SMEM 98304

__device__ __forceinline__ void load_chunk_n2(
    uint32_t st, const __half* __restrict__ A, const __half* __restrict__ B,
    size_t rowA0, size_t rowB0, int K3, int k0, int tid)
{
#pragma unroll
    for (int i = 0; i < 4; i++) {
        int u = tid + (i << 8);
        int row = u >> 3, kk = u & 7;
        uint32_t off = (uint32_t)(row * 128 + kk * 16);
        uint32_t sw = off ^ ((off >> 3) & 0x70);
        cp16(st + sw, A + (rowA0 + row) * (size_t)K3 + k0 + kk * 8);
    }
#pragma unroll
    for (int i = 0; i < 8; i++) {
        int u = tid + (i << 8);
        int row = u >> 3, kk = u & 7;
        uint32_t off = (uint32_t)(row * 128 + kk * 16);
        uint32_t sw = off ^ ((off >> 3) & 0x70);
        cp16(st + 16384 + sw, B + (rowB0 + row) * (size_t)K3 + k0 + kk * 8);
    }
}

__global__ __launch_bounds__(256) void gemm_mma2(
    const __half* __restrict__ A, const __half* __restrict__ B,
    const float* __restrict__ bias, const float* __restrict__ Y,
    float* __restrict__ Cf, double* __restrict__ red,
    int M, int N, int K3)
{
    extern __shared__ __align__(128) char smem[];
    uint32_t sbase = smem_u32(smem);

    int tid = threadIdx.x, lane = tid & 31, wid = tid >> 5;
    int warpM = wid >> 2, warpN = wid & 3;
    int tN = blockIdx.x, tM = blockIdx.y;
    size_t rowA0 = (size_t)tM * 128;
    size_t rowB0 = (size_t)tN * 256;
    int nch = K3 >> 6;

    float acc[4][8][4];
#pragma unroll
    for (int i = 0; i < 4; i++)
#pragma unroll
        for (int j = 0; j < 8; j++)
#pragma unroll
            for (int t = 0; t < 4; t++) acc[i][j][t] = 0.f;

    load_chunk_n2(sbase, A, B, rowA0, rowB0, K3, 0, tid);
    asm volatile("cp.async.commit_group;" ::: "memory");

    for (int c = 0; c < nch; c++) {
        if (c + 1 < nch) {
            uint32_t sb = sbase + (uint32_t)((c + 1) & 1) * 49152u;
            load_chunk_n2(sb, A, B, rowA0, rowB0, K3, (c + 1) << 6, tid);
            asm volatile("cp.async.commit_group;" ::: "memory");
            asm volatile("cp.async.wait_group 1;" ::: "memory");
        } else {
            asm volatile("cp.async.wait_group 0;" ::: "memory");
        }
        __syncthreads();

        uint32_t aB = sbase + (uint32_t)(c & 1) * 49152u;
        uint32_t bB = aB + 16384;
#pragma unroll
        for (int ks = 0; ks < 4; ks++) {
            uint32_t af[4][4], bf[4][4];
#pragma unroll
            for (int mf = 0; mf < 4; mf++) {
                int row = warpM * 64 + mf * 16 + (lane & 15);
                uint32_t off = (uint32_t)(row * 128 + ks * 32 + ((lane >> 4) << 4));
                off ^= (off >> 3) & 0x70;
                ldsm_x4(af[mf], aB + off);
            }
#pragma unroll
            for (int nf2 = 0; nf2 < 4; nf2++) {
                int row = warpN * 64 + nf2 * 16 + (lane & 15);
                uint32_t off = (uint32_t)(row * 128 + ks * 32 + ((lane >> 4) << 4));
                off ^= (off >> 3) & 0x70;
                ldsm_x4(bf[nf2], bB + off);
            }
#pragma unroll
            for (int mf = 0; mf < 4; mf++)
#pragma unroll
                for (int nf2 = 0; nf2 < 4; nf2++) {
                    mma16816(acc[mf][nf2 * 2],     af[mf], bf[nf2][0], bf[nf2][2]);
                    mma16816(acc[mf][nf2 * 2 + 1], af[mf], bf[nf2][1], bf[nf2][3]);
                }
        }
        __syncthreads();
    }

    int m0 = tM * 128 + warpM * 64;
    int n0 = tN * 256 + warpN * 64;
    double ls = 0.0, lq = 0.0;
#pragma unroll
    for (int mf = 0; mf < 4; mf++) {
#pragma unroll
        for (int nf = 0; nf < 8; nf++) {
            int r = m0 + mf * 16 + (lane >> 2);
            int col = n0 + nf * 8 + ((lane & 3) << 1);
            float b0 = bias ? __ldg(bias + col) : 0.f;
            float b1 = bias ? __ldg(bias + col + 1) : 0.f;
            float2 y0 = *(const float2*)(Y + (size_t)r * N + col);
            float2 y1 = *(const float2*)(Y + (size_t)(r + 8) * N + col);
            float s00 = acc[mf][nf][0] + b0 + y0.x;
            float s01 = acc[mf][nf][1] + b1 + y0.y;
            float s10 = acc[mf][nf][2] + b0 + y1.x;
            float s11 = acc[mf][nf][3] + b1 + y1.y;
            *(float2*)(Cf + (size_t)r * N + col) = make_float2(s00, s01);
            *(float2*)(Cf + (size_t)(r + 8) * N + col) = make_float2(s10, s11);
            ls += (double)s00 + (double)s01 + (double)s10 + (double)s11;
            lq += (double)s00 * s00 + (double)s01 * s01 +
                  (double)s10 * s10 + (double)s11 * s11;
        }
    }
#pragma unroll
    for (int o = 16; o > 0; o >>= 1) {
        ls += __shfl_down_sync(0xffffffffu, ls, o);
        lq += __shfl_down_sync(0xffffffffu, lq, o);
    }
    __shared__ double shs[8], shq[8];
    if (lane == 0) { shs[wid] = ls; shq[wid] = lq; }
    __syncthreads();
    if (tid == 0) {
        double ts = 0, tq = 0;
#pragma unroll
        for (int k = 0; k < 8; k++) { ts += shs[k]; tq += shq[k]; }
        atomicAdd(&red[0], ts);
        atomicAdd(&red[1], tq);
    }
}

// ================== edge GEMM: A-resident, all 3 blocks =======================
#define EG_SMEM 98304

__global__ __launch_bounds__(128) void gemm_edge(
    const __half* __restrict__ XE, const __half* __restrict__ WT,
    __half* __restrict__ EH)
{
    extern __shared__ __align__(128) char smem[];
    uint32_t sbase = smem_u32(smem);
    uint32_t bbase = sbase + 65536;

    int tid = threadIdx.x, lane = tid & 31, wid = tid >> 5;
    int warpM = wid >> 1, warpN = wid & 1;
    size_t rowA0 = (size_t)blockIdx.x * 128;

#pragma unroll
    for (int ch = 0; ch < 4; ch++) {
#pragma unroll
        for (int i = 0; i < 8; i++) {
            int u = tid + (i << 7);
            int row = u >> 3, kk = u & 7;
            uint32_t off = (uint32_t)(row * 128 + kk * 16);
            uint32_t sw = off ^ ((off >> 3) & 0x70);
            cp16(sbase + ch * 16384 + sw, XE + (rowA0 + row) * 256 + ch * 64 + kk * 8);
        }
    }
    {
#pragma unroll
        for (int i = 0; i < 8; i++) {
            int u = tid + (i << 7);
            int row = u >> 3, kk = u & 7;
            uint32_t off = (uint32_t)(row * 128 + kk * 16);
            uint32_t sw = off ^ ((off >> 3) & 0x70);
            cp16(bbase + sw, WT + OW_E + (size_t)row * 256 + kk * 8);
        }
    }
    asm volatile("cp.async.commit_group;" ::: "memory");

    float acc[4][8][4];
#pragma unroll
    for (int i = 0; i < 4; i++)
#pragma unroll
        for (int j = 0; j < 8; j++)
#pragma unroll
            for (int t = 0; t < 4; t++) acc[i][j][t] = 0.f;

    for (int it = 0; it < 24; it++) {
        if (it < 23) {
            int j = it + 1;
            int wt = j >> 2, ck = j & 3;
            int blkj = wt >> 1, nh = wt & 1;
            const __half* Bp = WT + (size_t)blkj * WB + OW_E;
            uint32_t bb = bbase + (uint32_t)(j & 1) * 16384u;
#pragma unroll
            for (int i = 0; i < 8; i++) {
                int u = tid + (i << 7);
                int row = u >> 3, kk = u & 7;
                uint32_t off = (uint32_t)(row * 128 + kk * 16);
                uint32_t sw = off ^ ((off >> 3) & 0x70);
                cp16(bb + sw, Bp + (size_t)(nh * 128 + row) * 256 + ck * 64 + kk * 8);
            }
            asm volatile("cp.async.commit_group;" ::: "memory");
            asm volatile("cp.async.wait_group 1;" ::: "memory");
        } else {
            asm volatile("cp.async.wait_group 0;" ::: "memory");
        }
        __syncthreads();

        int ck = it & 3;
        uint32_t aB = sbase + (uint32_t)ck * 16384u;
        uint32_t bB = bbase + (uint32_t)(it & 1) * 16384u;
#pragma unroll
        for (int ks = 0; ks < 4; ks++) {
            uint32_t af[4][4], bf[4][4];
#pragma unroll
            for (int mf = 0; mf < 4; mf++) {
                int row = warpM * 64 + mf * 16 + (lane & 15);
                uint32_t off = (uint32_t)(row * 128 + ks * 32 + ((lane >> 4) << 4));
                off ^= (off >> 3) & 0x70;
                ldsm_x4(af[mf], aB + off);
            }
#pragma unroll
            for (int nf2 = 0; nf2 < 4; nf2++) {
                int row = warpN * 64 + nf2 * 16 + (lane & 15);
                uint32_t off = (uint32_t)(row * 128 + ks * 32 + ((lane >> 4) << 4));
                off ^= (off >> 3) & 0x70;
                ldsm_x4(bf[nf2], bB + off);
            }
#pragma unroll
            for (int mf = 0; mf < 4; mf++)
#pragma unroll
                for (int nf2 = 0; nf2 < 4; nf2++) {
                    mma16816(acc[mf][nf2 * 2],     af[mf], bf[nf2][0], bf[nf2][2]);
                    mma16816(acc[mf][nf2 * 2 + 1], af[mf], bf[nf2][1], bf[nf2][3]);
                }
        }
        __syncthreads();

        if (ck == 3) {
            int wt = it >> 2;
            int blk = wt >> 1, nh = wt & 1;
            __half* out = EH + (size_t)blk * N_EDGES * DIM;
#pragma unroll
            for (int mf = 0; mf < 4; mf++) {
#pragma unroll
                for (int nf = 0; nf < 8; nf++) {
                    int r = (int)rowA0 + warpM * 64 + mf * 16 + (lane >> 2);
                    int col = nh * 128 + warpN * 64 + nf * 8 + ((lane & 3) << 1);
                    *(__half2*)(out + (size_t)r * DIM + col) =
                        __floats2half2_rn(acc[mf][nf][0], acc[mf][nf][1]);
                    *(__half2*)(out + (size_t)(r + 8) * DIM + col) =
                        __floats2half2_rn(acc[mf][nf][2], acc[mf][nf][3]);
#pragma unroll
                    for (int t = 0; t < 4; t++) acc[mf][nf][t] = 0.f;
                }
            }
        }
    }
}

// ---------------- CSR build ----------------------------------------------------
__global__ void zero_deg() {
    int i = blockIdx.x * blockDim.x + threadIdx.x;
    if (i < N_NODES) g_cursor[i] = 0;
    if (i < 12) g_red[i] = 0.0;
}
__global__ void hist_dst(const int* __restrict__ ei) {
    int i = blockIdx.x * blockDim.x + threadIdx.x;
    if (i < N_EDGES) atomicAdd(&g_cursor[ei[N_EDGES + i]], 1);
}
__global__ __launch_bounds__(1024) void scan16k() {
    __shared__ int warp_tot[32];
    int tid = threadIdx.x, lane = tid & 31, wid = tid >> 5;
    int base = tid * 16;
    int vals[16];
    int s = 0;
#pragma unroll
    for (int t = 0; t < 16; t++) {
        int idx = base + t;
        int v = (idx < N_NODES) ? g_cursor[idx] : 0;
        vals[t] = s;
        s += v;
    }
    int x = s;
#pragma unroll
    for (int o = 1; o < 32; o <<= 1) {
        int n = __shfl_up_sync(0xffffffffu, x, o);
        if (lane >= o) x += n;
    }
    if (lane == 31) warp_tot[wid] = x;
    __syncthreads();
    if (wid == 0) {
        int t = warp_tot[lane];
        int y = t;
#pragma unroll
        for (int o = 1; o < 32; o <<= 1) {
            int n = __shfl_up_sync(0xffffffffu, y, o);
            if (lane >= o) y += n;
        }
        warp_tot[lane] = y - t;
    }
    __syncthreads();
    int offset = warp_tot[wid] + (x - s);
#pragma unroll
    for (int t = 0; t < 16; t++) {
        int idx = base + t;
        if (idx < N_NODES) g_rowstart[idx] = offset + vals[t];
    }
    if (tid == 1023) g_rowstart[N_NODES] = offset + s;
    __syncthreads();
#pragma unroll
    for (int t = 0; t < 16; t++) {
        int idx = base + t;
        if (idx < N_NODES) g_cursor[idx] = g_rowstart[idx];
    }
}
__global__ void scatter_perm(const int* __restrict__ ei,
                             const float* __restrict__ xdist) {
    int i = blockIdx.x * blockDim.x + threadIdx.x;
    if (i < N_EDGES) {
        int d = ei[N_EDGES + i];
        int pos = atomicAdd(&g_cursor[d], 1);
        g_perm[pos] = i;
        g_src_s[pos] = ei[i];
        g_invd_s[pos] = 1.0f / xdist[i];
    }
}

// ---------------- converters ---------------------------------------------------
__global__ __launch_bounds__(256) void cvt_h(
    const float* __restrict__ s, __half* __restrict__ d, int n4)
{
    int i = blockIdx.x * blockDim.x + threadIdx.x;
    if (i >= n4) return;
    float4 v = ((const float4*)s)[i];
    *(uint2*)(d + (size_t)i * 4) =
        make_uint2(pack_h2(__float2half_rn(v.x), __float2half_rn(v.y)),
                   pack_h2(__float2half_rn(v.z), __float2half_rn(v.w)));
}

__global__ __launch_bounds__(256) void cvt_h_gather(
    const float* __restrict__ s, __half* __restrict__ d)
{
    int tid = blockIdx.x * blockDim.x + threadIdx.x;
    int row = tid >> 6;
    int col = (tid & 63) * 4;
    if (row >= N_EDGES) return;
    int srow = g_perm[row];
    float4 v = *(const float4*)(s + (size_t)srow * DIM + col);
    *(uint2*)(d + (size_t)row * DIM + col) =
        make_uint2(pack_h2(__float2half_rn(v.x), __float2half_rn(v.y)),
                   pack_h2(__float2half_rn(v.z), __float2half_rn(v.w)));
}

// ---------------- fused weight prep: all 21 transposes + bias pack -------------
// grid (836, 3), block (32, 8). tiles 0..831 = weight 32x32 transpose tiles;
// tiles 832..835 = bias pack (256 entries each).
__global__ void wprep(
    const float* __restrict__ Wq, const float* __restrict__ Wk,
    const float* __restrict__ Wv, const float* __restrict__ Ws,
    const float* __restrict__ We, const float* __restrict__ W1,
    const float* __restrict__ W2,
    const float* __restrict__ bq, const float* __restrict__ bk,
    const float* __restrict__ bv, const float* __restrict__ bs)
{
    int b = blockIdx.y;
    int t = blockIdx.x;
    __half* wtb = g_wt + (size_t)b * WB;

    if (t >= 832) {
        int tt = (t - 832) * 256 + threadIdx.y * 32 + threadIdx.x;
        float v = (tt < 256) ? bq[b * 256 + tt]
                : (tt < 512) ? bk[b * 256 + tt - 256]
                : (tt < 768) ? bv[b * 256 + tt - 512]
                             : bs[b * 256 + tt - 768];
        g_bqkvs[b * 1024 + tt] = v;
        return;
    }

    const float* W;
    __half* out;
    int K, N, tile;
    if (t < 320) {
        int m = t >> 6;
        tile = t & 63;
        const float* s = (m == 0) ? Wq : (m == 1) ? Wk : (m == 2) ? Wv
                       : (m == 3) ? Ws : We;
        W = s + (size_t)b * 65536;
        out = (m < 4) ? wtb + OW_QKVS + m * 256 * 256 : wtb + OW_E;
        K = 256; N = 256;
    } else if (t < 576) {
        tile = t - 320;
        W = W1 + (size_t)b * 262144;
        out = wtb + OW_1;
        K = 256; N = 1024;
    } else {
        tile = t - 576;
        W = W2 + (size_t)b * 262144;
        out = wtb + OW_2;
        K = 1024; N = 256;
    }
    int ntiles = N >> 5;
    int n0 = (tile % ntiles) * 32, k0 = (tile / ntiles) * 32;

    __shared__ float tsm[32][33];
    int tx = threadIdx.x, ty = threadIdx.y;
#pragma unroll
    for (int r = 0; r < 4; r++)
        tsm[ty + 8 * r][tx] = W[(size_t)(k0 + ty + 8 * r) * N + n0 + tx];
    __syncthreads();
#pragma unroll
    for (int r = 0; r < 4; r++) {
        int nl = ty + 8 * r;
        out[(size_t)(n0 + nl) * K + k0 + tx] = __float2half_rn(tsm[tx][nl]);
    }
}

// ------ fused CSR attention (software-pipelined) + skip + residual + LN red ----
__global__ __launch_bounds__(256) void attn_csr(
    const __half* __restrict__ eh, const float* __restrict__ x,
    float* __restrict__ y, double* __restrict__ red)
{
    int tid = threadIdx.x, lane = tid & 31, wid = tid >> 5;
    int node = blockIdx.x * 8 + wid;

    double ls = 0.0, lq = 0.0;
    if (node < N_NODES) {
        const float* qrow = g_q + (size_t)node * 256;
        float4 q0 = *(const float4*)(qrow + lane * 8);
        float4 q1 = *(const float4*)(qrow + lane * 8 + 4);

        int start = g_rowstart[node];
        int end   = g_rowstart[node + 1];

        float m0 = 0.f, m1 = 0.f, m2 = 0.f, m3 = 0.f;
        float m4 = 0.f, m5 = 0.f, m6 = 0.f, m7 = 0.f;
        float denom = 0.f;

        if (start < end) {
            // prime pipeline: load iteration `start`'s data
            int src_n = g_src_s[start];
            float invd_n = g_invd_s[start];
            const __half* kvr = g_kv + (size_t)src_n * 512 + lane * 8;
            int4 kv_n = *(const int4*)(kvr);
            int4 vv_n = *(const int4*)(kvr + 256);
            int4 ev_n = *(const int4*)(eh + (size_t)start * DIM + lane * 8);

            for (int j = start; j < end; j++) {
                int4 kvi = kv_n, vvi = vv_n, evi = ev_n;
                float invd = invd_n;
                if (j + 1 < end) {     // prefetch next iteration
                    int src2 = g_src_s[j + 1];
                    invd_n = g_invd_s[j + 1];
                    const __half* kvr2 = g_kv + (size_t)src2 * 512 + lane * 8;
                    kv_n = *(const int4*)(kvr2);
                    vv_n = *(const int4*)(kvr2 + 256);
                    ev_n = *(const int4*)(eh + (size_t)(j + 1) * DIM + lane * 8);
                }

                __half2* kp = (__half2*)&kvi;
                __half2* vp = (__half2*)&vvi;
                __half2* ep = (__half2*)&evi;
                float2 k0 = __half22float2(kp[0]), k1 = __half22float2(kp[1]);
                float2 k2 = __half22float2(kp[2]), k3 = __half22float2(kp[3]);
                float2 e0 = __half22float2(ep[0]), e1 = __half22float2(ep[1]);
                float2 e2 = __half22float2(ep[2]), e3 = __half22float2(ep[3]);

                float p = 0.f;
                p = fmaf(q0.x, k0.x + e0.x, p);
                p = fmaf(q0.y, k0.y + e0.y, p);
                p = fmaf(q0.z, k1.x + e1.x, p);
                p = fmaf(q0.w, k1.y + e1.y, p);
                p = fmaf(q1.x, k2.x + e2.x, p);
                p = fmaf(q1.y, k2.y + e2.y, p);
                p = fmaf(q1.z, k3.x + e3.x, p);
                p = fmaf(q1.w, k3.y + e3.y, p);
                p += __shfl_xor_sync(0xffffffffu, p, 1);
                p += __shfl_xor_sync(0xffffffffu, p, 2);

                float ex = __expf(p * invd * RSQRT_DH);
                denom += ex;

                float2 v0 = __half22float2(vp[0]), v1 = __half22float2(vp[1]);
                float2 v2 = __half22float2(vp[2]), v3 = __half22float2(vp[3]);
                m0 = fmaf(v0.x + e0.x, ex, m0);
                m1 = fmaf(v0.y + e0.y, ex, m1);
                m2 = fmaf(v1.x + e1.x, ex, m2);
                m3 = fmaf(v1.y + e1.y, ex, m3);
                m4 = fmaf(v2.x + e2.x, ex, m4);
                m5 = fmaf(v2.y + e2.y, ex, m5);
                m6 = fmaf(v3.x + e3.x, ex, m6);
                m7 = fmaf(v3.y + e3.y, ex, m7);
            }
        }

        float inv = 1.0f / (denom + 1e-16f);
        const float* xr = x + (size_t)node * 256 + lane * 8;
        const float* sk = g_skip + (size_t)node * 256 + lane * 8;
        float4 xv0 = *(const float4*)(xr);
        float4 xv1 = *(const float4*)(xr + 4);
        float4 sk0 = *(const float4*)(sk);
        float4 sk1 = *(const float4*)(sk + 4);

        float r0 = xv0.x + sk0.x + m0 * inv;
        float r1 = xv0.y + sk0.y + m1 * inv;
        float r2 = xv0.z + sk0.z + m2 * inv;
        float r3 = xv0.w + sk0.w + m3 * inv;
        float r4 = xv1.x + sk1.x + m4 * inv;
        float r5 = xv1.y + sk1.y + m5 * inv;
        float r6 = xv1.z + sk1.z + m6 * inv;
        float r7 = xv1.w + sk1.w + m7 * inv;

        float* yp = y + (size_t)node * 256 + lane * 8;
        *(float4*)(yp)     = make_float4(r0, r1, r2, r3);
        *(float4*)(yp + 4) = make_float4(r4, r5, r6, r7);

        ls = (double)r0 + (double)r1 + (double)r2 + (double)r3 +
             (double)r4 + (double)r5 + (double)r6 + (double)r7;
        lq = (double)r0 * r0 + (double)r1 * r1 + (double)r2 * r2 + (double)r3 * r3 +
             (double)r4 * r4 + (double)r5 * r5 + (double)r6 * r6 + (double)r7 * r7;
    }

#pragma unroll
    for (int o = 16; o > 0; o >>= 1) {
        ls += __shfl_down_sync(0xffffffffu, ls, o);
        lq += __shfl_down_sync(0xffffffffu, lq, o);
    }
    __shared__ double shs[8], shq[8];
    if (lane == 0) { shs[wid] = ls; shq[wid] = lq; }
    __syncthreads();
    if (tid == 0) {
        double ts = 0, tq = 0;
#pragma unroll
        for (int k = 0; k < 8; k++) { ts += shs[k]; tq += shq[k]; }
        atomicAdd(&red[0], ts);
        atomicAdd(&red[1], tq);
    }
}

// ---------------- graph layernorm apply + optional plain fp16 emit -------------
__global__ __launch_bounds__(256) void lnapply(
    const float* __restrict__ y, const float* __restrict__ g,
    const float* __restrict__ b, float* __restrict__ o,
    __half* __restrict__ oh, const double* __restrict__ red)
{
    int i = blockIdx.x * blockDim.x + threadIdx.x;
    double mean = red[0] / (double)LN_CNT;
    double var  = red[1] / (double)LN_CNT - mean * mean;
    if (var < 0) var = 0;
    float inv = 1.0f / ((float)sqrt(var) + LN_EPS);
    float mu = (float)mean;

    int i4 = i * 4;
    int c = i4 % DIM;
    float4 yv = ((const float4*)y)[i];
    float4 gv = *(const float4*)(g + c);
    float4 bv = *(const float4*)(b + c);
    float4 r;
    r.x = (yv.x - mu) * inv * gv.x + bv.x;
    r.y = (yv.y - mu) * inv * gv.y + bv.y;
    r.z = (yv.z - mu) * inv * gv.z + bv.z;
    r.w = (yv.w - mu) * inv * gv.w + bv.w;
    ((float4*)o)[i] = r;

    if (oh) {
        *(uint2*)(oh + (size_t)i4) =
            make_uint2(pack_h2(__float2half_rn(r.x), __float2half_rn(r.y)),
                       pack_h2(__float2half_rn(r.z), __float2half_rn(r.w)));
    }
}

// ---------------- host orchestration -------------------------------------------
extern "C" void kernel_launch(void* const* d_in, const int* in_sizes, int n_in,
                              void* d_out, int out_size)
{
    const float* x_in   = (const float*)d_in[0];
    const int*   ei     = (const int*)d_in[1];
    const float* x_edge = (const float*)d_in[2];
    const float* x_dist = (const float*)d_in[3];
    const float* Wq_a   = (const float*)d_in[4];
    const float* bq_a   = (const float*)d_in[5];
    const float* Wk_a   = (const float*)d_in[6];
    const float* bk_a   = (const float*)d_in[7];
    const float* Wv_a   = (const float*)d_in[8];
    const float* bv_a   = (const float*)d_in[9];
    const float* We_a   = (const float*)d_in[10];
    const float* Ws_a   = (const float*)d_in[11];
    const float* bs_a   = (const float*)d_in[12];
    const float* g1_a   = (const float*)d_in[13];
    const float* b1_a   = (const float*)d_in[14];
    const float* W1_a   = (const float*)d_in[15];
    const float* c1_a   = (const float*)d_in[16];
    const float* W2_a   = (const float*)d_in[17];
    const float* c2_a   = (const float*)d_in[18];
    const float* g2_a   = (const float*)d_in[19];
    const float* b2_a   = (const float*)d_in[20];

    static int smem_set = 0;
    if (!smem_set) {
        cudaFuncSetAttribute(gemm_mma, cudaFuncAttributeMaxDynamicSharedMemorySize, NG_SMEM);
        cudaFuncSetAttribute(gemm_mma2, cudaFuncAttributeMaxDynamicSharedMemorySize, NG2_SMEM);
        cudaFuncSetAttribute(gemm_edge, cudaFuncAttributeMaxDynamicSharedMemorySize, EG_SMEM);
        smem_set = 1;
    }

    float *out_, *y_, *x_, *bqkvs_;
    double* red_;
    __half *eh3_, *xeh_, *xh_, *yh_, *hh_, *wt_;
    cudaGetSymbolAddress((void**)&eh3_,  g_e_h3);
    cudaGetSymbolAddress((void**)&out_,  g_out);
    cudaGetSymbolAddress((void**)&y_,    g_y);
    cudaGetSymbolAddress((void**)&x_,    g_x);
    cudaGetSymbolAddress((void**)&red_,  g_red);
    cudaGetSymbolAddress((void**)&bqkvs_, g_bqkvs);
    cudaGetSymbolAddress((void**)&xeh_,  g_xe_h);
    cudaGetSymbolAddress((void**)&xh_,   g_x_h);
    cudaGetSymbolAddress((void**)&yh_,   g_y_h);
    cudaGetSymbolAddress((void**)&hh_,   g_h_h);
    cudaGetSymbolAddress((void**)&wt_,   g_wt);

    const int elem4 = LN_CNT / 4;

    // CSR build (also zeroes the 12 LN accumulators)
    zero_deg<<<(N_NODES + 255) / 256, 256>>>();
    hist_dst<<<(N_EDGES + 255) / 256, 256>>>(ei);
    scan16k<<<1, 1024>>>();
    scatter_perm<<<(N_EDGES + 255) / 256, 256>>>(ei, x_dist);

    // conversions + fused weight prep
    cvt_h<<<(elem4 + 255) / 256, 256>>>(x_in, xh_, elem4);
    cvt_h_gather<<<(N_EDGES * 64) / 256, 256>>>(x_edge, xeh_);
    wprep<<<dim3(836, 3), dim3(32, 8)>>>(Wq_a, Wk_a, Wv_a, Ws_a, We_a, W1_a, W2_a,
                                         bq_a, bk_a, bv_a, bs_a);

    // edge projections for all blocks, output already CSR-ordered
    gemm_edge<<<N_EDGES / 128, 128, EG_SMEM>>>(xeh_, wt_, eh3_);

    const float* xcur = x_in;
    const __half* xhcur = xh_;
    for (int blk = 0; blk < 3; blk++) {
        size_t wb = (size_t)blk * WB;
        const float* g1 = g1_a + blk * DIM;
        const float* b1 = b1_a + blk * DIM;
        const float* c1 = c1_a + blk * HID;
        const float* c2 = c2_a + blk * DIM;
        const float* g2 = g2_a + blk * DIM;
        const float* b2 = b2_a + blk * DIM;
        double* redb = red_ + blk * 4;

        gemm_mma<<<dim3(8, 125), 128, NG_SMEM>>>(
            xhcur, wt_ + wb + OW_QKVS, bqkvs_ + blk * 1024,
            nullptr, N_NODES, 1024, 256, 0, 2);

        attn_csr<<<N_NODES / 8, 256>>>(eh3_ + (size_t)blk * N_EDGES * DIM,
                                       xcur, y_, redb + 0);
        lnapply<<<elem4 / 256, 256>>>(y_, g1, b1, y_, yh_, redb + 0);

        gemm_mma<<<dim3(8, 125), 128, NG_SMEM>>>(
            yh_, wt_ + wb + OW_1, c1, hh_, N_NODES, HID, 256, 1, 1);
        gemm_mma2<<<dim3(1, 125), 256, NG2_SMEM>>>(
            hh_, wt_ + wb + OW_2, c2, y_, out_, redb + 2, N_NODES, DIM, 1024);

        float* xdst = (blk == 2) ? (float*)d_out : x_;
        __half* xhdst = (blk == 2) ? nullptr : xh_;
        lnapply<<<elem4 / 256, 256>>>(out_, g2, b2, xdst, xhdst, redb + 2);

        xcur = x_;
        xhcur = xh_;
    }
}